// round 1
// baseline (speedup 1.0000x reference)
#include <cuda_runtime.h>
#include <math.h>

#define LQ 2048
#define DM 256
#define NH 4
#define HDIM 64
#define NLAYER 6
#define MMEM 8192
#define VOCAB 50257
#define DFF 1024

// ---------------- scratch (device globals: allocation-free) ----------------
__device__ float g_x[LQ * DM];
__device__ float g_xn[LQ * DM];
__device__ float g_qkv[LQ * 3 * DM];
__device__ float g_o[LQ * DM];
__device__ float g_h1[LQ * DFF];
__device__ float g_kn[MMEM * DM];
__device__ float g_res[(size_t)LQ * MMEM];   // 64 MB resonance scores
__device__ float g_ret[LQ * DM];
__device__ float g_xout[LQ * DM];
__device__ float g_need[LQ];
__device__ float g_sal[LQ];
__device__ float g_gate[LQ];

// ---------------- embedding lookup ----------------
__global__ void k_embed(const int* __restrict__ tokens, const float* __restrict__ embed,
                        float* __restrict__ x) {
    int idx = blockIdx.x * 256 + threadIdx.x;
    int l = idx >> 8, d = idx & 255;
    x[idx] = embed[(size_t)tokens[l] * DM + d];
}

// ---------------- rmsnorm (block per row, 256 threads) ----------------
__global__ void k_rmsnorm(const float* __restrict__ x, const float* __restrict__ w,
                          float* __restrict__ xn) {
    int l = blockIdx.x, t = threadIdx.x;
    __shared__ float red[256];
    float v = x[l * DM + t];
    red[t] = v * v;
    __syncthreads();
    for (int s = 128; s > 0; s >>= 1) {
        if (t < s) red[t] += red[t + s];
        __syncthreads();
    }
    float r = rsqrtf(red[0] / (float)DM + 1e-6f);
    xn[l * DM + t] = v * r * w[t];
}

// ---------------- generic tiled GEMM: C[M,N] = A[M,K] * op(B) (+bias,+res,+gelu)
// b_nt=1: B is [N,K] row-major (C = A * B^T); b_nt=0: B is [K,N] row-major.
// Requires M % 64 == 0 and K % 16 == 0 (true for all call sites). N guarded.
__global__ void k_gemm(const float* __restrict__ A, const float* __restrict__ B,
                       const float* __restrict__ bias, const float* __restrict__ resid,
                       float* __restrict__ C, int Mm, int Nn, int Kk,
                       int b_nt, int act) {
    __shared__ float As[16][65];
    __shared__ float Bs[16][65];
    int n0 = blockIdx.x * 64, m0 = blockIdx.y * 64;
    int tid = threadIdx.x;          // 256
    int tx = tid & 15, ty = tid >> 4;
    float acc[4][4] = {};
    for (int k0 = 0; k0 < Kk; k0 += 16) {
        {   // A tile 64x16 -> As[k][m]
            int k = tid & 15, mb = tid >> 4;
#pragma unroll
            for (int r = 0; r < 4; r++) {
                int m = mb + r * 16;
                As[k][m] = A[(size_t)(m0 + m) * Kk + k0 + k];
            }
        }
        if (b_nt) {                 // B[N,K] -> Bs[k][n]
            int k = tid & 15, nb = tid >> 4;
#pragma unroll
            for (int r = 0; r < 4; r++) {
                int n = nb + r * 16, gn = n0 + n;
                Bs[k][n] = (gn < Nn) ? B[(size_t)gn * Kk + k0 + k] : 0.f;
            }
        } else {                    // B[K,N] -> Bs[k][n]
            int n = tid & 63, kb = tid >> 6;
#pragma unroll
            for (int r = 0; r < 4; r++) {
                int k = kb + r * 4, gn = n0 + n;
                Bs[k][n] = (gn < Nn) ? B[(size_t)(k0 + k) * Nn + gn] : 0.f;
            }
        }
        __syncthreads();
#pragma unroll
        for (int kk = 0; kk < 16; kk++) {
            float a[4], b[4];
#pragma unroll
            for (int i = 0; i < 4; i++) a[i] = As[kk][ty * 4 + i];
#pragma unroll
            for (int j = 0; j < 4; j++) b[j] = Bs[kk][tx * 4 + j];
#pragma unroll
            for (int i = 0; i < 4; i++)
#pragma unroll
                for (int j = 0; j < 4; j++) acc[i][j] += a[i] * b[j];
        }
        __syncthreads();
    }
#pragma unroll
    for (int i = 0; i < 4; i++) {
        int m = m0 + ty * 4 + i;
#pragma unroll
        for (int j = 0; j < 4; j++) {
            int n = n0 + tx * 4 + j;
            if (n < Nn) {
                float c = acc[i][j];
                if (bias) c += bias[n];
                if (resid) c += resid[(size_t)m * Nn + n];
                if (act == 1) c = 0.5f * c * (1.0f + erff(c * 0.70710678118654752f));
                C[(size_t)m * Nn + n] = c;
            }
        }
    }
}

// ---------------- RoPE on q and k inside qkv buffer ----------------
__global__ void k_rope(float* __restrict__ qkv) {
    int l = blockIdx.x, t = threadIdx.x;   // 128 threads = 4 heads x 32 pairs
    int h = t >> 5, i = t & 31;
    float inv = (float)pow(10000.0, -(double)(2 * i) / (double)HDIM);
    float ang = (float)l * inv;
    float s, c;
    sincosf(ang, &s, &c);
    float* qp = qkv + (size_t)l * 768 + h * HDIM + 2 * i;
    float q0 = qp[0], q1 = qp[1];
    qp[0] = q0 * c - q1 * s;
    qp[1] = q0 * s + q1 * c;
    float* kp = qp + DM;
    float k0 = kp[0], k1 = kp[1];
    kp[0] = k0 * c - k1 * s;
    kp[1] = k0 * s + k1 * c;
}

// ---------------- causal attention: one block per (query,head), 128 threads ----
__global__ void k_attn(const float* __restrict__ qkv, float* __restrict__ o) {
    int q = blockIdx.x, h = blockIdx.y, t = threadIdx.x;   // 128 threads
    __shared__ float qv[HDIM];
    __shared__ float s[LQ];
    __shared__ float red[128];
    if (t < HDIM) qv[t] = qkv[(size_t)q * 768 + h * HDIM + t];
    __syncthreads();
    float lmax = -INFINITY;
    for (int k = t; k <= q; k += 128) {
        const float4* kp = (const float4*)(qkv + (size_t)k * 768 + DM + h * HDIM);
        float d = 0.f;
#pragma unroll
        for (int i = 0; i < 16; i++) {
            float4 kv = kp[i];
            d += qv[4 * i] * kv.x + qv[4 * i + 1] * kv.y +
                 qv[4 * i + 2] * kv.z + qv[4 * i + 3] * kv.w;
        }
        d *= 0.125f;   // 1/sqrt(64)
        s[k] = d;
        lmax = fmaxf(lmax, d);
    }
    red[t] = lmax; __syncthreads();
    for (int st = 64; st > 0; st >>= 1) { if (t < st) red[t] = fmaxf(red[t], red[t + st]); __syncthreads(); }
    float mx = red[0]; __syncthreads();
    float lsum = 0.f;
    for (int k = t; k <= q; k += 128) { float p = expf(s[k] - mx); s[k] = p; lsum += p; }
    red[t] = lsum; __syncthreads();
    for (int st = 64; st > 0; st >>= 1) { if (t < st) red[t] += red[t + st]; __syncthreads(); }
    float denom = red[0]; __syncthreads();
    int d = t & 63, part = t >> 6;
    float acc = 0.f;
    for (int k = part; k <= q; k += 2)
        acc += s[k] * qkv[(size_t)k * 768 + 2 * DM + h * HDIM + d];
    red[t] = acc; __syncthreads();
    if (t < 64) o[(size_t)q * DM + h * HDIM + t] = (red[t] + red[t + 64]) / denom;
}

// ---------------- row stats: qn + need/sal/gate sigmoids ----------------
__global__ void k_rowstats(const float* __restrict__ x,
                           const float* __restrict__ unc_w, const float* __restrict__ unc_b,
                           const float* __restrict__ sal_w, const float* __restrict__ sal_b,
                           const float* __restrict__ wg_w, const float* __restrict__ wg_b,
                           float* __restrict__ qn, float* __restrict__ need,
                           float* __restrict__ sal, float* __restrict__ gate) {
    int l = blockIdx.x, t = threadIdx.x;
    __shared__ float r0[256], r1[256], r2[256], r3[256];
    float v = x[l * DM + t];
    r0[t] = v * v;
    r1[t] = v * unc_w[t];
    r2[t] = v * sal_w[t];
    r3[t] = v * wg_w[t];
    __syncthreads();
    for (int s = 128; s > 0; s >>= 1) {
        if (t < s) { r0[t] += r0[t + s]; r1[t] += r1[t + s]; r2[t] += r2[t + s]; r3[t] += r3[t + s]; }
        __syncthreads();
    }
    float norm = sqrtf(r0[0]);
    qn[l * DM + t] = v / fmaxf(norm, 1e-12f);
    if (t == 0) {
        need[l] = 1.f / (1.f + expf(-(r1[0] + unc_b[0])));
        sal[l]  = 1.f / (1.f + expf(-(r2[0] + sal_b[0])));
        gate[l] = 1.f / (1.f + expf(-(r3[0] + wg_b[0])));
    }
}

// ---------------- normalize memory keys ----------------
__global__ void k_knorm(const float* __restrict__ mk, float* __restrict__ kn) {
    int m = blockIdx.x, t = threadIdx.x;
    __shared__ float red[256];
    float v = mk[(size_t)m * DM + t];
    red[t] = v * v;
    __syncthreads();
    for (int s = 128; s > 0; s >>= 1) { if (t < s) red[t] += red[t + s]; __syncthreads(); }
    kn[(size_t)m * DM + t] = v / fmaxf(sqrtf(red[0]), 1e-12f);
}

// ---------------- row softmax over memory slots (scale 5.0) ----------------
__global__ void k_softmax_mem(float* __restrict__ res) {
    int l = blockIdx.x, t = threadIdx.x;
    __shared__ float red[256];
    float* row = res + (size_t)l * MMEM;
    float lm = -INFINITY;
    for (int m = t; m < MMEM; m += 256) lm = fmaxf(lm, row[m] * 5.0f);
    red[t] = lm; __syncthreads();
    for (int s = 128; s > 0; s >>= 1) { if (t < s) red[t] = fmaxf(red[t], red[t + s]); __syncthreads(); }
    float mx = red[0]; __syncthreads();
    float ls = 0.f;
    for (int m = t; m < MMEM; m += 256) { float p = expf(row[m] * 5.0f - mx); row[m] = p; ls += p; }
    red[t] = ls; __syncthreads();
    for (int s = 128; s > 0; s >>= 1) { if (t < s) red[t] += red[t + s]; __syncthreads(); }
    float inv = 1.f / red[0];
    __syncthreads();
    for (int m = t; m < MMEM; m += 256) row[m] *= inv;
}

// ---------------- retrieved *= need[l] ----------------
__global__ void k_need(float* __restrict__ ret, const float* __restrict__ need) {
    int idx = blockIdx.x * 256 + threadIdx.x;
    ret[idx] *= need[idx >> 8];
}

// ---------------- gate penalty (single block) ----------------
__global__ void k_penalty(const float* __restrict__ sal, const float* __restrict__ gate,
                          float* __restrict__ out) {
    __shared__ float s[LQ];
    __shared__ float rn[256], rc[256];
    int t = threadIdx.x;
    for (int l = t; l < LQ; l += 256) s[l] = sal[l];
    __syncthreads();
    float num = 0.f, cnt = 0.f;
    for (int l = t; l < LQ; l += 256) {
        float v = s[l];
        int j0 = l - 15 < 0 ? 0 : l - 15;
        int j1 = l + 15 > LQ - 1 ? LQ - 1 : l + 15;
        float mx = -INFINITY;
        for (int j = j0; j <= j1; j++) mx = fmaxf(mx, s[j]);
        if (v == mx && v > 0.15f) {
            float g = gate[l];
            num += (1.f - g) * (1.f - g);
            cnt += 1.f;
        }
    }
    rn[t] = num; rc[t] = cnt;
    __syncthreads();
    for (int st = 128; st > 0; st >>= 1) {
        if (t < st) { rn[t] += rn[t + st]; rc[t] += rc[t + st]; }
        __syncthreads();
    }
    if (t == 0) out[0] = rc[0] > 0.f ? rn[0] / fmaxf(rc[0], 1.f) : 0.f;
}

// ---------------- host side ----------------
static void gemm(const float* A, const float* B, const float* bias, const float* resid,
                 float* C, int Mm, int Nn, int Kk, int b_nt, int act) {
    dim3 grid((Nn + 63) / 64, (Mm + 63) / 64);
    k_gemm<<<grid, 256>>>(A, B, bias, resid, C, Mm, Nn, Kk, b_nt, act);
}

extern "C" void kernel_launch(void* const* d_in, const int* in_sizes, int n_in,
                              void* d_out, int out_size) {
    const int*   tokens    = (const int*)d_in[0];
    const float* embed     = (const float*)d_in[1];
    const float* qkv_w     = (const float*)d_in[2];
    const float* qkv_b     = (const float*)d_in[3];
    const float* proj_w    = (const float*)d_in[4];
    const float* proj_b    = (const float*)d_in[5];
    const float* ln1_w     = (const float*)d_in[6];
    const float* mlp_w1    = (const float*)d_in[7];
    const float* mlp_b1    = (const float*)d_in[8];
    const float* mlp_w2    = (const float*)d_in[9];
    const float* mlp_b2    = (const float*)d_in[10];
    const float* ln2_w     = (const float*)d_in[11];
    const float* sal_w     = (const float*)d_in[12];
    const float* sal_b     = (const float*)d_in[13];
    const float* unc_w     = (const float*)d_in[14];
    const float* unc_b     = (const float*)d_in[15];
    const float* wg_w      = (const float*)d_in[16];
    const float* wg_b      = (const float*)d_in[17];
    const float* memproj_w = (const float*)d_in[18];
    const float* memproj_b = (const float*)d_in[19];
    const float* mem_k     = (const float*)d_in[20];
    const float* mem_v     = (const float*)d_in[21];
    float* out = (float*)d_out;

    float *x, *xn, *qkv, *o, *h1, *kn, *res, *ret, *xout, *need, *sal, *gate;
    cudaGetSymbolAddress((void**)&x, g_x);
    cudaGetSymbolAddress((void**)&xn, g_xn);
    cudaGetSymbolAddress((void**)&qkv, g_qkv);
    cudaGetSymbolAddress((void**)&o, g_o);
    cudaGetSymbolAddress((void**)&h1, g_h1);
    cudaGetSymbolAddress((void**)&kn, g_kn);
    cudaGetSymbolAddress((void**)&res, g_res);
    cudaGetSymbolAddress((void**)&ret, g_ret);
    cudaGetSymbolAddress((void**)&xout, g_xout);
    cudaGetSymbolAddress((void**)&need, g_need);
    cudaGetSymbolAddress((void**)&sal, g_sal);
    cudaGetSymbolAddress((void**)&gate, g_gate);

    // embed + memory-key normalization (independent)
    k_embed<<<(LQ * DM) / 256, 256>>>(tokens, embed, x);
    k_knorm<<<MMEM, 256>>>(mem_k, kn);

    // transformer layers
    for (int li = 0; li < NLAYER; li++) {
        k_rmsnorm<<<LQ, 256>>>(x, ln1_w + li * DM, xn);
        gemm(xn, qkv_w + (size_t)li * 3 * DM * DM, qkv_b + li * 3 * DM, nullptr,
             qkv, LQ, 3 * DM, DM, 1, 0);
        k_rope<<<LQ, 128>>>(qkv);
        {
            dim3 grid(LQ, NH);
            k_attn<<<grid, 128>>>(qkv, o);
        }
        gemm(o, proj_w + (size_t)li * DM * DM, proj_b + li * DM, x,
             x, LQ, DM, DM, 1, 0);
        k_rmsnorm<<<LQ, 256>>>(x, ln2_w + li * DM, xn);
        gemm(xn, mlp_w1 + (size_t)li * DFF * DM, mlp_b1 + li * DFF, nullptr,
             h1, LQ, DFF, DM, 1, 1);
        gemm(h1, mlp_w2 + (size_t)li * DM * DFF, mlp_b2 + li * DM, x,
             x, LQ, DM, DFF, 1, 0);
    }

    // landmark memory read
    k_rowstats<<<LQ, 256>>>(x, unc_w, unc_b, sal_w, sal_b, wg_w, wg_b,
                            xn, need, sal, gate);
    gemm(xn, kn, nullptr, nullptr, res, LQ, MMEM, DM, 1, 0);
    k_softmax_mem<<<LQ, 256>>>(res);
    gemm(res, mem_v, nullptr, nullptr, ret, LQ, DM, MMEM, 0, 0);
    k_need<<<(LQ * DM) / 256, 256>>>(ret, need);
    gemm(ret, memproj_w, memproj_b, x, xout, LQ, DM, DM, 1, 0);

    // tied-head logits
    gemm(xout, embed, nullptr, nullptr, out, LQ, VOCAB, DM, 1, 0);

    // gate penalty appended after logits
    if (out_size > LQ * VOCAB)
        k_penalty<<<1, 256>>>(sal, gate, out + (size_t)LQ * VOCAB);
}

// round 3
// speedup vs baseline: 1.0223x; 1.0223x over previous
#include <cuda_runtime.h>
#include <math.h>
#include <stdint.h>

#define LQ 2048
#define DM 256
#define NH 4
#define HDIM 64
#define NLAYER 6
#define MMEM 8192
#define VOCAB 50257
#define DFF 1024

// ---------------- scratch (device globals: allocation-free) ----------------
__device__ float g_x[LQ * DM];
__device__ float g_xn[LQ * DM];
__device__ float g_qkv[LQ * 3 * DM];
__device__ float g_o[LQ * DM];
__device__ float g_h1[LQ * DFF];
__device__ float g_kn[MMEM * DM];
__device__ float g_res[(size_t)LQ * MMEM];   // 64 MB resonance scores
__device__ float g_ret[LQ * DM];
__device__ float g_xout[LQ * DM];
__device__ float g_need[LQ];
__device__ float g_sal[LQ];
__device__ float g_gate[LQ];

__device__ __forceinline__ uint32_t f2tf32(float f) {
    uint32_t u;
    asm("cvt.rna.tf32.f32 %0, %1;" : "=r"(u) : "f"(f));
    return u;
}
// split f into big(tf32) + small(tf32 of remainder)
__device__ __forceinline__ void tf32_split(float f, uint32_t& b, uint32_t& s) {
    b = f2tf32(f);
    s = f2tf32(f - __uint_as_float(b));
}

// ---------------- embedding lookup ----------------
__global__ void k_embed(const int* __restrict__ tokens, const float* __restrict__ embed,
                        float* __restrict__ x) {
    int idx = blockIdx.x * 256 + threadIdx.x;
    int l = idx >> 8, d = idx & 255;
    x[idx] = embed[(size_t)tokens[l] * DM + d];
}

// ---------------- rmsnorm (block per row, 256 threads) ----------------
__global__ void k_rmsnorm(const float* __restrict__ x, const float* __restrict__ w,
                          float* __restrict__ xn) {
    int l = blockIdx.x, t = threadIdx.x;
    __shared__ float red[256];
    float v = x[l * DM + t];
    red[t] = v * v;
    __syncthreads();
    for (int s = 128; s > 0; s >>= 1) {
        if (t < s) red[t] += red[t + s];
        __syncthreads();
    }
    float r = rsqrtf(red[0] / (float)DM + 1e-6f);
    xn[l * DM + t] = v * r * w[t];
}

// ---------------- tf32x3 tensor-core GEMM ----------------
// C[M,N] = A[M,K] * op(B) (+bias, +resid, +gelu), fp32-accurate via 3xTF32.
// b_nt=1: B is [N,K] row-major (C = A*B^T); b_nt=0: B is [K,N] row-major.
// Requires M % 128 == 0, K % 32 == 0. N guarded.
// Block tile 128x128, K-chunk 32, 256 threads (8 warps, 2x4 warp grid, 64x32/warp).
#define SMS 36   // smem row stride in floats (pad 32->36, 16B-aligned)
#define TILE_U32 (128 * SMS)
__global__ void __launch_bounds__(256)
k_gemm(const float* __restrict__ A, const float* __restrict__ B,
       const float* __restrict__ bias, const float* __restrict__ resid,
       float* __restrict__ C, int Mm, int Nn, int Kk,
       int b_nt, int act) {
    extern __shared__ uint32_t smem[];
    uint32_t* AsB = smem;
    uint32_t* AsS = smem + TILE_U32;
    uint32_t* BsB = smem + 2 * TILE_U32;
    uint32_t* BsS = smem + 3 * TILE_U32;

    const int n0 = blockIdx.x * 128, m0 = blockIdx.y * 128;
    const int tid = threadIdx.x;
    const int w = tid >> 5, lane = tid & 31;
    const int g = lane >> 2, l4 = lane & 3;
    const int warp_m = (w >> 2) * 64;   // 0 or 64
    const int warp_n = (w & 3) * 32;    // 0,32,64,96

    float acc[4][4][4];
#pragma unroll
    for (int i = 0; i < 4; i++)
#pragma unroll
        for (int j = 0; j < 4; j++)
#pragma unroll
            for (int r = 0; r < 4; r++) acc[i][j][r] = 0.f;

    for (int k0 = 0; k0 < Kk; k0 += 32) {
        // ---- load A tile [128 x 32] -> AsB/AsS[m][k] ----
        {
            int row = tid >> 1, phase = tid & 1;
            const float4* src = (const float4*)(A + (size_t)(m0 + row) * Kk + k0);
#pragma unroll
            for (int i = 0; i < 4; i++) {
                float4 v = src[phase * 4 + i];
                int off = row * SMS + (phase * 4 + i) * 4;
                tf32_split(v.x, AsB[off + 0], AsS[off + 0]);
                tf32_split(v.y, AsB[off + 1], AsS[off + 1]);
                tf32_split(v.z, AsB[off + 2], AsS[off + 2]);
                tf32_split(v.w, AsB[off + 3], AsS[off + 3]);
            }
        }
        // ---- load B tile -> BsB/BsS[n][k] ----
        if (b_nt) {
            int row = tid >> 1, phase = tid & 1;
            int gn = n0 + row;
            if (gn < Nn) {
                const float4* src = (const float4*)(B + (size_t)gn * Kk + k0);
#pragma unroll
                for (int i = 0; i < 4; i++) {
                    float4 v = src[phase * 4 + i];
                    int off = row * SMS + (phase * 4 + i) * 4;
                    tf32_split(v.x, BsB[off + 0], BsS[off + 0]);
                    tf32_split(v.y, BsB[off + 1], BsS[off + 1]);
                    tf32_split(v.z, BsB[off + 2], BsS[off + 2]);
                    tf32_split(v.w, BsB[off + 3], BsS[off + 3]);
                }
            } else {
#pragma unroll
                for (int i = 0; i < 4; i++) {
                    int off = row * SMS + (phase * 4 + i) * 4;
#pragma unroll
                    for (int c = 0; c < 4; c++) { BsB[off + c] = 0u; BsS[off + c] = 0u; }
                }
            }
        } else {  // B[K,N]: transpose load
            int n = tid & 127, kb = (tid >> 7) * 16;
            int gn = n0 + n;
#pragma unroll
            for (int i = 0; i < 16; i++) {
                int k = kb + i;
                int off = n * SMS + k;
                if (gn < Nn) tf32_split(B[(size_t)(k0 + k) * Nn + gn], BsB[off], BsS[off]);
                else { BsB[off] = 0u; BsS[off] = 0u; }
            }
        }
        __syncthreads();

        // ---- compute: 3xTF32 per 8-k step ----
#pragma unroll
        for (int ks = 0; ks < 4; ks++) {
            const int kc = ks * 8;
            uint32_t af[4][4], bfb[4][2], bfx[4][2];
#pragma unroll
            for (int mt = 0; mt < 4; mt++) {
                int r0 = (warp_m + mt * 16 + g) * SMS + kc + l4;
                af[mt][0] = AsB[r0];
                af[mt][1] = AsB[r0 + 8 * SMS];
                af[mt][2] = AsB[r0 + 4];
                af[mt][3] = AsB[r0 + 8 * SMS + 4];
            }
#pragma unroll
            for (int nt = 0; nt < 4; nt++) {
                int nr = (warp_n + nt * 8 + g) * SMS + kc + l4;
                bfb[nt][0] = BsB[nr];
                bfb[nt][1] = BsB[nr + 4];
                bfx[nt][0] = BsS[nr];
                bfx[nt][1] = BsS[nr + 4];
            }
            // big*big
#pragma unroll
            for (int mt = 0; mt < 4; mt++)
#pragma unroll
                for (int nt = 0; nt < 4; nt++) {
                    float* c = acc[mt][nt];
                    asm volatile(
                        "mma.sync.aligned.m16n8k8.row.col.f32.tf32.tf32.f32 "
                        "{%0,%1,%2,%3}, {%4,%5,%6,%7}, {%8,%9}, {%0,%1,%2,%3};\n"
                        : "+f"(c[0]), "+f"(c[1]), "+f"(c[2]), "+f"(c[3])
                        : "r"(af[mt][0]), "r"(af[mt][1]), "r"(af[mt][2]), "r"(af[mt][3]),
                          "r"(bfb[nt][0]), "r"(bfb[nt][1]));
                }
            // big*small
#pragma unroll
            for (int mt = 0; mt < 4; mt++)
#pragma unroll
                for (int nt = 0; nt < 4; nt++) {
                    float* c = acc[mt][nt];
                    asm volatile(
                        "mma.sync.aligned.m16n8k8.row.col.f32.tf32.tf32.f32 "
                        "{%0,%1,%2,%3}, {%4,%5,%6,%7}, {%8,%9}, {%0,%1,%2,%3};\n"
                        : "+f"(c[0]), "+f"(c[1]), "+f"(c[2]), "+f"(c[3])
                        : "r"(af[mt][0]), "r"(af[mt][1]), "r"(af[mt][2]), "r"(af[mt][3]),
                          "r"(bfx[nt][0]), "r"(bfx[nt][1]));
                }
            // small*big (reload af with small parts)
#pragma unroll
            for (int mt = 0; mt < 4; mt++) {
                int r0 = (warp_m + mt * 16 + g) * SMS + kc + l4;
                af[mt][0] = AsS[r0];
                af[mt][1] = AsS[r0 + 8 * SMS];
                af[mt][2] = AsS[r0 + 4];
                af[mt][3] = AsS[r0 + 8 * SMS + 4];
            }
#pragma unroll
            for (int mt = 0; mt < 4; mt++)
#pragma unroll
                for (int nt = 0; nt < 4; nt++) {
                    float* c = acc[mt][nt];
                    asm volatile(
                        "mma.sync.aligned.m16n8k8.row.col.f32.tf32.tf32.f32 "
                        "{%0,%1,%2,%3}, {%4,%5,%6,%7}, {%8,%9}, {%0,%1,%2,%3};\n"
                        : "+f"(c[0]), "+f"(c[1]), "+f"(c[2]), "+f"(c[3])
                        : "r"(af[mt][0]), "r"(af[mt][1]), "r"(af[mt][2]), "r"(af[mt][3]),
                          "r"(bfb[nt][0]), "r"(bfb[nt][1]));
                }
        }
        __syncthreads();
    }

    // ---- epilogue ----
#pragma unroll
    for (int mt = 0; mt < 4; mt++) {
#pragma unroll
        for (int nt = 0; nt < 4; nt++) {
#pragma unroll
            for (int half = 0; half < 2; half++) {
                int m = m0 + warp_m + mt * 16 + g + half * 8;
#pragma unroll
                for (int cc = 0; cc < 2; cc++) {
                    int n = n0 + warp_n + nt * 8 + l4 * 2 + cc;
                    if (n < Nn) {
                        float c = acc[mt][nt][half * 2 + cc];
                        if (bias) c += bias[n];
                        if (resid) c += resid[(size_t)m * Nn + n];
                        if (act == 1) c = 0.5f * c * (1.0f + erff(c * 0.70710678118654752f));
                        C[(size_t)m * Nn + n] = c;
                    }
                }
            }
        }
    }
}
#define GEMM_SMEM (4 * TILE_U32 * 4)

// ---------------- RoPE on q and k inside qkv buffer ----------------
__global__ void k_rope(float* __restrict__ qkv) {
    int l = blockIdx.x, t = threadIdx.x;   // 128 threads = 4 heads x 32 pairs
    int h = t >> 5, i = t & 31;
    float inv = (float)pow(10000.0, -(double)(2 * i) / (double)HDIM);
    float ang = (float)l * inv;
    float s, c;
    sincosf(ang, &s, &c);
    float* qp = qkv + (size_t)l * 768 + h * HDIM + 2 * i;
    float q0 = qp[0], q1 = qp[1];
    qp[0] = q0 * c - q1 * s;
    qp[1] = q0 * s + q1 * c;
    float* kp = qp + DM;
    float k0 = kp[0], k1 = kp[1];
    kp[0] = k0 * c - k1 * s;
    kp[1] = k0 * s + k1 * c;
}

// ---------------- causal attention: one block per (query,head), 128 threads ----
__global__ void k_attn(const float* __restrict__ qkv, float* __restrict__ o) {
    int q = blockIdx.x, h = blockIdx.y, t = threadIdx.x;   // 128 threads
    __shared__ float qv[HDIM];
    __shared__ float s[LQ];
    __shared__ float red[128];
    if (t < HDIM) qv[t] = qkv[(size_t)q * 768 + h * HDIM + t];
    __syncthreads();
    float lmax = -INFINITY;
    for (int k = t; k <= q; k += 128) {
        const float4* kp = (const float4*)(qkv + (size_t)k * 768 + DM + h * HDIM);
        float d = 0.f;
#pragma unroll
        for (int i = 0; i < 16; i++) {
            float4 kv = kp[i];
            d += qv[4 * i] * kv.x + qv[4 * i + 1] * kv.y +
                 qv[4 * i + 2] * kv.z + qv[4 * i + 3] * kv.w;
        }
        d *= 0.125f;   // 1/sqrt(64)
        s[k] = d;
        lmax = fmaxf(lmax, d);
    }
    red[t] = lmax; __syncthreads();
    for (int st = 64; st > 0; st >>= 1) { if (t < st) red[t] = fmaxf(red[t], red[t + st]); __syncthreads(); }
    float mx = red[0]; __syncthreads();
    float lsum = 0.f;
    for (int k = t; k <= q; k += 128) { float p = expf(s[k] - mx); s[k] = p; lsum += p; }
    red[t] = lsum; __syncthreads();
    for (int st = 64; st > 0; st >>= 1) { if (t < st) red[t] += red[t + st]; __syncthreads(); }
    float denom = red[0]; __syncthreads();
    int d = t & 63, part = t >> 6;
    float acc = 0.f;
    for (int k = part; k <= q; k += 2)
        acc += s[k] * qkv[(size_t)k * 768 + 2 * DM + h * HDIM + d];
    red[t] = acc; __syncthreads();
    if (t < 64) o[(size_t)q * DM + h * HDIM + t] = (red[t] + red[t + 64]) / denom;
}

// ---------------- row stats: qn + need/sal/gate sigmoids ----------------
__global__ void k_rowstats(const float* __restrict__ x,
                           const float* __restrict__ unc_w, const float* __restrict__ unc_b,
                           const float* __restrict__ sal_w, const float* __restrict__ sal_b,
                           const float* __restrict__ wg_w, const float* __restrict__ wg_b,
                           float* __restrict__ qn, float* __restrict__ need,
                           float* __restrict__ sal, float* __restrict__ gate) {
    int l = blockIdx.x, t = threadIdx.x;
    __shared__ float r0[256], r1[256], r2[256], r3[256];
    float v = x[l * DM + t];
    r0[t] = v * v;
    r1[t] = v * unc_w[t];
    r2[t] = v * sal_w[t];
    r3[t] = v * wg_w[t];
    __syncthreads();
    for (int s = 128; s > 0; s >>= 1) {
        if (t < s) { r0[t] += r0[t + s]; r1[t] += r1[t + s]; r2[t] += r2[t + s]; r3[t] += r3[t + s]; }
        __syncthreads();
    }
    float norm = sqrtf(r0[0]);
    qn[l * DM + t] = v / fmaxf(norm, 1e-12f);
    if (t == 0) {
        need[l] = 1.f / (1.f + expf(-(r1[0] + unc_b[0])));
        sal[l]  = 1.f / (1.f + expf(-(r2[0] + sal_b[0])));
        gate[l] = 1.f / (1.f + expf(-(r3[0] + wg_b[0])));
    }
}

// ---------------- normalize memory keys ----------------
__global__ void k_knorm(const float* __restrict__ mk, float* __restrict__ kn) {
    int m = blockIdx.x, t = threadIdx.x;
    __shared__ float red[256];
    float v = mk[(size_t)m * DM + t];
    red[t] = v * v;
    __syncthreads();
    for (int s = 128; s > 0; s >>= 1) { if (t < s) red[t] += red[t + s]; __syncthreads(); }
    kn[(size_t)m * DM + t] = v / fmaxf(sqrtf(red[0]), 1e-12f);
}

// ---------------- row softmax over memory slots (scale 5.0) ----------------
__global__ void k_softmax_mem(float* __restrict__ res) {
    int l = blockIdx.x, t = threadIdx.x;
    __shared__ float red[256];
    float* row = res + (size_t)l * MMEM;
    float lm = -INFINITY;
    for (int m = t; m < MMEM; m += 256) lm = fmaxf(lm, row[m] * 5.0f);
    red[t] = lm; __syncthreads();
    for (int s = 128; s > 0; s >>= 1) { if (t < s) red[t] = fmaxf(red[t], red[t + s]); __syncthreads(); }
    float mx = red[0]; __syncthreads();
    float ls = 0.f;
    for (int m = t; m < MMEM; m += 256) { float p = expf(row[m] * 5.0f - mx); row[m] = p; ls += p; }
    red[t] = ls; __syncthreads();
    for (int s = 128; s > 0; s >>= 1) { if (t < s) red[t] += red[t + s]; __syncthreads(); }
    float inv = 1.f / red[0];
    __syncthreads();
    for (int m = t; m < MMEM; m += 256) row[m] *= inv;
}

// ---------------- retrieved *= need[l] ----------------
__global__ void k_need(float* __restrict__ ret, const float* __restrict__ need) {
    int idx = blockIdx.x * 256 + threadIdx.x;
    ret[idx] *= need[idx >> 8];
}

// ---------------- gate penalty (single block) ----------------
__global__ void k_penalty(const float* __restrict__ sal, const float* __restrict__ gate,
                          float* __restrict__ out) {
    __shared__ float s[LQ];
    __shared__ float rn[256], rc[256];
    int t = threadIdx.x;
    for (int l = t; l < LQ; l += 256) s[l] = sal[l];
    __syncthreads();
    float num = 0.f, cnt = 0.f;
    for (int l = t; l < LQ; l += 256) {
        float v = s[l];
        int j0 = l - 15 < 0 ? 0 : l - 15;
        int j1 = l + 15 > LQ - 1 ? LQ - 1 : l + 15;
        float mx = -INFINITY;
        for (int j = j0; j <= j1; j++) mx = fmaxf(mx, s[j]);
        if (v == mx && v > 0.15f) {
            float g = gate[l];
            num += (1.f - g) * (1.f - g);
            cnt += 1.f;
        }
    }
    rn[t] = num; rc[t] = cnt;
    __syncthreads();
    for (int st = 128; st > 0; st >>= 1) {
        if (t < st) { rn[t] += rn[t + st]; rc[t] += rc[t + st]; }
        __syncthreads();
    }
    if (t == 0) out[0] = rc[0] > 0.f ? rn[0] / fmaxf(rc[0], 1.f) : 0.f;
}

// ---------------- host side ----------------
static void gemm(const float* A, const float* B, const float* bias, const float* resid,
                 float* C, int Mm, int Nn, int Kk, int b_nt, int act) {
    dim3 grid((Nn + 127) / 128, Mm / 128);
    k_gemm<<<grid, 256, GEMM_SMEM>>>(A, B, bias, resid, C, Mm, Nn, Kk, b_nt, act);
}

extern "C" void kernel_launch(void* const* d_in, const int* in_sizes, int n_in,
                              void* d_out, int out_size) {
    const int*   tokens    = (const int*)d_in[0];
    const float* embed     = (const float*)d_in[1];
    const float* qkv_w     = (const float*)d_in[2];
    const float* qkv_b     = (const float*)d_in[3];
    const float* proj_w    = (const float*)d_in[4];
    const float* proj_b    = (const float*)d_in[5];
    const float* ln1_w     = (const float*)d_in[6];
    const float* mlp_w1    = (const float*)d_in[7];
    const float* mlp_b1    = (const float*)d_in[8];
    const float* mlp_w2    = (const float*)d_in[9];
    const float* mlp_b2    = (const float*)d_in[10];
    const float* ln2_w     = (const float*)d_in[11];
    const float* sal_w     = (const float*)d_in[12];
    const float* sal_b     = (const float*)d_in[13];
    const float* unc_w     = (const float*)d_in[14];
    const float* unc_b     = (const float*)d_in[15];
    const float* wg_w      = (const float*)d_in[16];
    const float* wg_b      = (const float*)d_in[17];
    const float* memproj_w = (const float*)d_in[18];
    const float* memproj_b = (const float*)d_in[19];
    const float* mem_k     = (const float*)d_in[20];
    const float* mem_v     = (const float*)d_in[21];
    float* out = (float*)d_out;

    static int smem_set = 0;
    if (!smem_set) {
        cudaFuncSetAttribute(k_gemm, cudaFuncAttributeMaxDynamicSharedMemorySize, GEMM_SMEM);
        smem_set = 1;
    }

    float *x, *xn, *qkv, *o, *h1, *kn, *res, *ret, *xout, *need, *sal, *gate;
    cudaGetSymbolAddress((void**)&x, g_x);
    cudaGetSymbolAddress((void**)&xn, g_xn);
    cudaGetSymbolAddress((void**)&qkv, g_qkv);
    cudaGetSymbolAddress((void**)&o, g_o);
    cudaGetSymbolAddress((void**)&h1, g_h1);
    cudaGetSymbolAddress((void**)&kn, g_kn);
    cudaGetSymbolAddress((void**)&res, g_res);
    cudaGetSymbolAddress((void**)&ret, g_ret);
    cudaGetSymbolAddress((void**)&xout, g_xout);
    cudaGetSymbolAddress((void**)&need, g_need);
    cudaGetSymbolAddress((void**)&sal, g_sal);
    cudaGetSymbolAddress((void**)&gate, g_gate);

    // embed + memory-key normalization (independent)
    k_embed<<<(LQ * DM) / 256, 256>>>(tokens, embed, x);
    k_knorm<<<MMEM, 256>>>(mem_k, kn);

    // transformer layers
    for (int li = 0; li < NLAYER; li++) {
        k_rmsnorm<<<LQ, 256>>>(x, ln1_w + li * DM, xn);
        gemm(xn, qkv_w + (size_t)li * 3 * DM * DM, qkv_b + li * 3 * DM, nullptr,
             qkv, LQ, 3 * DM, DM, 1, 0);
        k_rope<<<LQ, 128>>>(qkv);
        {
            dim3 grid(LQ, NH);
            k_attn<<<grid, 128>>>(qkv, o);
        }
        gemm(o, proj_w + (size_t)li * DM * DM, proj_b + li * DM, x,
             x, LQ, DM, DM, 1, 0);
        k_rmsnorm<<<LQ, 256>>>(x, ln2_w + li * DM, xn);
        gemm(xn, mlp_w1 + (size_t)li * DFF * DM, mlp_b1 + li * DFF, nullptr,
             h1, LQ, DFF, DM, 1, 1);
        gemm(h1, mlp_w2 + (size_t)li * DM * DFF, mlp_b2 + li * DM, x,
             x, LQ, DM, DFF, 1, 0);
    }

    // landmark memory read
    k_rowstats<<<LQ, 256>>>(x, unc_w, unc_b, sal_w, sal_b, wg_w, wg_b,
                            xn, need, sal, gate);
    gemm(xn, kn, nullptr, nullptr, res, LQ, MMEM, DM, 1, 0);
    k_softmax_mem<<<LQ, 256>>>(res);
    gemm(res, mem_v, nullptr, nullptr, ret, LQ, DM, MMEM, 0, 0);
    k_need<<<(LQ * DM) / 256, 256>>>(ret, need);
    gemm(ret, memproj_w, memproj_b, x, xout, LQ, DM, DM, 1, 0);

    // tied-head logits
    gemm(xout, embed, nullptr, nullptr, out, LQ, VOCAB, DM, 1, 0);

    // gate penalty appended after logits
    if (out_size > LQ * VOCAB)
        k_penalty<<<1, 256>>>(sal, gate, out + (size_t)LQ * VOCAB);
}

// round 4
// speedup vs baseline: 1.3977x; 1.3673x over previous
#include <cuda_runtime.h>
#include <math.h>
#include <stdint.h>

#define LQ 2048
#define DM 256
#define NH 4
#define HDIM 64
#define NLAYER 6
#define MMEM 8192
#define VOCAB 50257
#define DFF 1024

// ---------------- scratch (device globals: allocation-free) ----------------
__device__ float g_x[LQ * DM];
__device__ float g_xn[LQ * DM];
__device__ float g_qkv[LQ * 3 * DM];
__device__ float g_o[LQ * DM];
__device__ float g_h1[LQ * DFF];
__device__ float g_kn[MMEM * DM];
__device__ float g_res[(size_t)LQ * MMEM];   // 64 MB resonance scores
__device__ float g_ret[LQ * DM];
__device__ float g_xout[LQ * DM];
__device__ float g_split[8 * LQ * DM];       // split-K partials (16 MB max)
__device__ float g_need[LQ];
__device__ float g_sal[LQ];
__device__ float g_gate[LQ];

__device__ __forceinline__ uint32_t f2tf32(float f) {
    uint32_t u;
    asm("cvt.rna.tf32.f32 %0, %1;" : "=r"(u) : "f"(f));
    return u;
}
__device__ __forceinline__ void tf32_split(float f, uint32_t& b, uint32_t& s) {
    b = f2tf32(f);
    s = f2tf32(f - __uint_as_float(b));
}
__device__ __forceinline__ void cp16(float* dst, const float* src, bool ok) {
    uint32_t sa = (uint32_t)__cvta_generic_to_shared(dst);
    int sz = ok ? 16 : 0;
    asm volatile("cp.async.ca.shared.global [%0], [%1], 16, %2;\n"
                 :: "r"(sa), "l"(src), "r"(sz));
}

// ---------------- embedding lookup ----------------
__global__ void k_embed(const int* __restrict__ tokens, const float* __restrict__ embed,
                        float* __restrict__ x) {
    int idx = blockIdx.x * 256 + threadIdx.x;
    int l = idx >> 8, d = idx & 255;
    x[idx] = embed[(size_t)tokens[l] * DM + d];
}

// ---------------- rmsnorm ----------------
__global__ void k_rmsnorm(const float* __restrict__ x, const float* __restrict__ w,
                          float* __restrict__ xn) {
    int l = blockIdx.x, t = threadIdx.x;
    __shared__ float red[256];
    float v = x[l * DM + t];
    red[t] = v * v;
    __syncthreads();
    for (int s = 128; s > 0; s >>= 1) {
        if (t < s) red[t] += red[t + s];
        __syncthreads();
    }
    float r = rsqrtf(red[0] / (float)DM + 1e-6f);
    xn[l * DM + t] = v * r * w[t];
}

// ---------------- tf32x3 pipelined GEMM ----------------
// C[M,N] = A[M,K] * op(B) (+bias,+resid,+gelu), fp32-accurate (3xTF32).
// b_nt=1: B is [N,K] (C=A*B^T); b_nt=0: B is [K,N].
// Block tile 128x128, K-chunk 32, double-buffered cp.async staging of RAW fp32;
// tf32 big/small split happens at fragment-read time in registers.
// kseg = K-range handled per CTA (blockIdx.z selects segment).
// If gridDim.z>1, raw partial sums go to C + z*M*N (no bias/resid/act).
#define ASTRIDE 36    // 128x32 A tile rows padded to 36 floats
#define BSTRIDE 132   // 32x128 B tile (b_nt=0) rows padded to 132 floats
#define STG 4608      // floats per stage buffer (128*36 = 4608 >= 32*132 = 4224)
#define GEMM_SMEM (4 * STG * 4)
__global__ void __launch_bounds__(256)
k_gemm(const float* __restrict__ A, const float* __restrict__ B,
       const float* __restrict__ bias, const float* __restrict__ resid,
       float* __restrict__ C, int Mm, int Nn, int Kk,
       int b_nt, int act, int kseg) {
    extern __shared__ float smem[];
    float* As = smem;                // [2][STG]
    float* Bs = smem + 2 * STG;      // [2][STG]

    const int n0 = blockIdx.x * 128, m0 = blockIdx.y * 128;
    const int tid = threadIdx.x;
    const int w = tid >> 5, lane = tid & 31;
    const int g = lane >> 2, l4 = lane & 3;
    const int warp_m = (w >> 2) * 64;
    const int warp_n = (w & 3) * 32;
    const int kbeg = blockIdx.z * kseg;
    const int kend = kbeg + kseg;

    float acc[4][4][4];
#pragma unroll
    for (int i = 0; i < 4; i++)
#pragma unroll
        for (int j = 0; j < 4; j++)
#pragma unroll
            for (int r = 0; r < 4; r++) acc[i][j][r] = 0.f;

    // ---- tile loader (cp.async; 4 x 16B per thread per tile) ----
    auto load_tiles = [&](int k0, int st) {
        {
            int row = tid >> 1, colb = (tid & 1) * 16;
            const float* src = A + (size_t)(m0 + row) * Kk + k0 + colb;
            float* dst = As + st * STG + row * ASTRIDE + colb;
#pragma unroll
            for (int i = 0; i < 4; i++) cp16(dst + i * 4, src + i * 4, true);
        }
        if (b_nt) {
            int row = tid >> 1, colb = (tid & 1) * 16;
            int gn = n0 + row;
            bool ok = gn < Nn;
            const float* src = B + (size_t)(ok ? gn : 0) * Kk + k0 + colb;
            float* dst = Bs + st * STG + row * ASTRIDE + colb;
#pragma unroll
            for (int i = 0; i < 4; i++) cp16(dst + i * 4, src + i * 4, ok);
        } else {
            int k = tid >> 3, colb = (tid & 7) * 16;
            const float* src = B + (size_t)(k0 + k) * Nn + n0 + colb;
            float* dst = Bs + st * STG + k * BSTRIDE + colb;
#pragma unroll
            for (int i = 0; i < 4; i++) cp16(dst + i * 4, src + i * 4, true);
        }
        asm volatile("cp.async.commit_group;\n");
    };

    load_tiles(kbeg, 0);
    int stage = 0;
    for (int k0 = kbeg; k0 < kend; k0 += 32) {
        bool more = (k0 + 32) < kend;
        if (more) {
            load_tiles(k0 + 32, stage ^ 1);
            asm volatile("cp.async.wait_group 1;\n");
        } else {
            asm volatile("cp.async.wait_group 0;\n");
        }
        __syncthreads();

        const float* Af = As + stage * STG;
        const float* Bf = Bs + stage * STG;
#pragma unroll
        for (int ks = 0; ks < 4; ks++) {
            const int kc = ks * 8;
            uint32_t ab[4][4], ax[4][4];
#pragma unroll
            for (int mt = 0; mt < 4; mt++) {
                int r = (warp_m + mt * 16 + g) * ASTRIDE + kc + l4;
                tf32_split(Af[r],                ab[mt][0], ax[mt][0]);
                tf32_split(Af[r + 8 * ASTRIDE],  ab[mt][1], ax[mt][1]);
                tf32_split(Af[r + 4],            ab[mt][2], ax[mt][2]);
                tf32_split(Af[r + 8 * ASTRIDE + 4], ab[mt][3], ax[mt][3]);
            }
            uint32_t bb[4][2], bx[4][2];
            if (b_nt) {
#pragma unroll
                for (int nt = 0; nt < 4; nt++) {
                    int r = (warp_n + nt * 8 + g) * ASTRIDE + kc + l4;
                    tf32_split(Bf[r],     bb[nt][0], bx[nt][0]);
                    tf32_split(Bf[r + 4], bb[nt][1], bx[nt][1]);
                }
            } else {
#pragma unroll
                for (int nt = 0; nt < 4; nt++) {
                    int cn = warp_n + nt * 8 + g;
                    tf32_split(Bf[(kc + l4) * BSTRIDE + cn],     bb[nt][0], bx[nt][0]);
                    tf32_split(Bf[(kc + l4 + 4) * BSTRIDE + cn], bb[nt][1], bx[nt][1]);
                }
            }
#define MMA(c, A0, A1, A2, A3, B0, B1)                                        \
    asm volatile("mma.sync.aligned.m16n8k8.row.col.f32.tf32.tf32.f32 "        \
                 "{%0,%1,%2,%3}, {%4,%5,%6,%7}, {%8,%9}, {%0,%1,%2,%3};\n"    \
                 : "+f"(c[0]), "+f"(c[1]), "+f"(c[2]), "+f"(c[3])             \
                 : "r"(A0), "r"(A1), "r"(A2), "r"(A3), "r"(B0), "r"(B1))
#pragma unroll
            for (int mt = 0; mt < 4; mt++)
#pragma unroll
                for (int nt = 0; nt < 4; nt++)
                    MMA(acc[mt][nt], ab[mt][0], ab[mt][1], ab[mt][2], ab[mt][3],
                        bb[nt][0], bb[nt][1]);
#pragma unroll
            for (int mt = 0; mt < 4; mt++)
#pragma unroll
                for (int nt = 0; nt < 4; nt++)
                    MMA(acc[mt][nt], ab[mt][0], ab[mt][1], ab[mt][2], ab[mt][3],
                        bx[nt][0], bx[nt][1]);
#pragma unroll
            for (int mt = 0; mt < 4; mt++)
#pragma unroll
                for (int nt = 0; nt < 4; nt++)
                    MMA(acc[mt][nt], ax[mt][0], ax[mt][1], ax[mt][2], ax[mt][3],
                        bb[nt][0], bb[nt][1]);
#undef MMA
        }
        __syncthreads();
        stage ^= 1;
    }

    // ---- epilogue ----
    float* Cw = C;
    bool partial = (gridDim.z > 1);
    if (partial) Cw = C + (size_t)blockIdx.z * Mm * Nn;
#pragma unroll
    for (int mt = 0; mt < 4; mt++) {
#pragma unroll
        for (int nt = 0; nt < 4; nt++) {
#pragma unroll
            for (int half = 0; half < 2; half++) {
                int m = m0 + warp_m + mt * 16 + g + half * 8;
#pragma unroll
                for (int cc = 0; cc < 2; cc++) {
                    int n = n0 + warp_n + nt * 8 + l4 * 2 + cc;
                    if (n < Nn) {
                        float c = acc[mt][nt][half * 2 + cc];
                        if (!partial) {
                            if (bias) c += bias[n];
                            if (resid) c += resid[(size_t)m * Nn + n];
                            if (act == 1) c = 0.5f * c * (1.0f + erff(c * 0.70710678118654752f));
                        }
                        Cw[(size_t)m * Nn + n] = c;
                    }
                }
            }
        }
    }
}

// ---------------- split-K reduction ----------------
__global__ void k_sreduce(const float* __restrict__ P, const float* __restrict__ bias,
                          const float* __restrict__ resid, float* __restrict__ C,
                          int Nn, int total, int nseg) {
    int idx = blockIdx.x * 256 + threadIdx.x;
    if (idx >= total) return;
    float s = 0.f;
    for (int z = 0; z < nseg; z++) s += P[(size_t)z * total + idx];
    int n = idx % Nn;
    if (bias) s += bias[n];
    if (resid) s += resid[idx];
    C[idx] = s;
}

// ---------------- RoPE ----------------
__global__ void k_rope(float* __restrict__ qkv) {
    int l = blockIdx.x, t = threadIdx.x;
    int h = t >> 5, i = t & 31;
    float inv = (float)pow(10000.0, -(double)(2 * i) / (double)HDIM);
    float ang = (float)l * inv;
    float s, c;
    sincosf(ang, &s, &c);
    float* qp = qkv + (size_t)l * 768 + h * HDIM + 2 * i;
    float q0 = qp[0], q1 = qp[1];
    qp[0] = q0 * c - q1 * s;
    qp[1] = q0 * s + q1 * c;
    float* kp = qp + DM;
    float k0 = kp[0], k1 = kp[1];
    kp[0] = k0 * c - k1 * s;
    kp[1] = k0 * s + k1 * c;
}

// ---------------- causal attention ----------------
__global__ void k_attn(const float* __restrict__ qkv, float* __restrict__ o) {
    int q = blockIdx.x, h = blockIdx.y, t = threadIdx.x;
    __shared__ float qv[HDIM];
    __shared__ float s[LQ];
    __shared__ float red[128];
    if (t < HDIM) qv[t] = qkv[(size_t)q * 768 + h * HDIM + t];
    __syncthreads();
    float lmax = -INFINITY;
    for (int k = t; k <= q; k += 128) {
        const float4* kp = (const float4*)(qkv + (size_t)k * 768 + DM + h * HDIM);
        float d = 0.f;
#pragma unroll
        for (int i = 0; i < 16; i++) {
            float4 kv = kp[i];
            d += qv[4 * i] * kv.x + qv[4 * i + 1] * kv.y +
                 qv[4 * i + 2] * kv.z + qv[4 * i + 3] * kv.w;
        }
        d *= 0.125f;
        s[k] = d;
        lmax = fmaxf(lmax, d);
    }
    red[t] = lmax; __syncthreads();
    for (int st = 64; st > 0; st >>= 1) { if (t < st) red[t] = fmaxf(red[t], red[t + st]); __syncthreads(); }
    float mx = red[0]; __syncthreads();
    float lsum = 0.f;
    for (int k = t; k <= q; k += 128) { float p = expf(s[k] - mx); s[k] = p; lsum += p; }
    red[t] = lsum; __syncthreads();
    for (int st = 64; st > 0; st >>= 1) { if (t < st) red[t] += red[t + st]; __syncthreads(); }
    float denom = red[0]; __syncthreads();
    int d = t & 63, part = t >> 6;
    float acc = 0.f;
    for (int k = part; k <= q; k += 2)
        acc += s[k] * qkv[(size_t)k * 768 + 2 * DM + h * HDIM + d];
    red[t] = acc; __syncthreads();
    if (t < 64) o[(size_t)q * DM + h * HDIM + t] = (red[t] + red[t + 64]) / denom;
}

// ---------------- row stats ----------------
__global__ void k_rowstats(const float* __restrict__ x,
                           const float* __restrict__ unc_w, const float* __restrict__ unc_b,
                           const float* __restrict__ sal_w, const float* __restrict__ sal_b,
                           const float* __restrict__ wg_w, const float* __restrict__ wg_b,
                           float* __restrict__ qn, float* __restrict__ need,
                           float* __restrict__ sal, float* __restrict__ gate) {
    int l = blockIdx.x, t = threadIdx.x;
    __shared__ float r0[256], r1[256], r2[256], r3[256];
    float v = x[l * DM + t];
    r0[t] = v * v;
    r1[t] = v * unc_w[t];
    r2[t] = v * sal_w[t];
    r3[t] = v * wg_w[t];
    __syncthreads();
    for (int s = 128; s > 0; s >>= 1) {
        if (t < s) { r0[t] += r0[t + s]; r1[t] += r1[t + s]; r2[t] += r2[t + s]; r3[t] += r3[t + s]; }
        __syncthreads();
    }
    float norm = sqrtf(r0[0]);
    qn[l * DM + t] = v / fmaxf(norm, 1e-12f);
    if (t == 0) {
        need[l] = 1.f / (1.f + expf(-(r1[0] + unc_b[0])));
        sal[l]  = 1.f / (1.f + expf(-(r2[0] + sal_b[0])));
        gate[l] = 1.f / (1.f + expf(-(r3[0] + wg_b[0])));
    }
}

// ---------------- normalize memory keys ----------------
__global__ void k_knorm(const float* __restrict__ mk, float* __restrict__ kn) {
    int m = blockIdx.x, t = threadIdx.x;
    __shared__ float red[256];
    float v = mk[(size_t)m * DM + t];
    red[t] = v * v;
    __syncthreads();
    for (int s = 128; s > 0; s >>= 1) { if (t < s) red[t] += red[t + s]; __syncthreads(); }
    kn[(size_t)m * DM + t] = v / fmaxf(sqrtf(red[0]), 1e-12f);
}

// ---------------- row softmax over memory slots ----------------
__global__ void k_softmax_mem(float* __restrict__ res) {
    int l = blockIdx.x, t = threadIdx.x;
    __shared__ float red[256];
    float* row = res + (size_t)l * MMEM;
    float lm = -INFINITY;
    for (int m = t; m < MMEM; m += 256) lm = fmaxf(lm, row[m] * 5.0f);
    red[t] = lm; __syncthreads();
    for (int s = 128; s > 0; s >>= 1) { if (t < s) red[t] = fmaxf(red[t], red[t + s]); __syncthreads(); }
    float mx = red[0]; __syncthreads();
    float ls = 0.f;
    for (int m = t; m < MMEM; m += 256) { float p = expf(row[m] * 5.0f - mx); row[m] = p; ls += p; }
    red[t] = ls; __syncthreads();
    for (int s = 128; s > 0; s >>= 1) { if (t < s) red[t] += red[t + s]; __syncthreads(); }
    float inv = 1.f / red[0];
    __syncthreads();
    for (int m = t; m < MMEM; m += 256) row[m] *= inv;
}

// ---------------- retrieved *= need[l] ----------------
__global__ void k_need(float* __restrict__ ret, const float* __restrict__ need) {
    int idx = blockIdx.x * 256 + threadIdx.x;
    ret[idx] *= need[idx >> 8];
}

// ---------------- gate penalty ----------------
__global__ void k_penalty(const float* __restrict__ sal, const float* __restrict__ gate,
                          float* __restrict__ out) {
    __shared__ float s[LQ];
    __shared__ float rn[256], rc[256];
    int t = threadIdx.x;
    for (int l = t; l < LQ; l += 256) s[l] = sal[l];
    __syncthreads();
    float num = 0.f, cnt = 0.f;
    for (int l = t; l < LQ; l += 256) {
        float v = s[l];
        int j0 = l - 15 < 0 ? 0 : l - 15;
        int j1 = l + 15 > LQ - 1 ? LQ - 1 : l + 15;
        float mx = -INFINITY;
        for (int j = j0; j <= j1; j++) mx = fmaxf(mx, s[j]);
        if (v == mx && v > 0.15f) {
            float g = gate[l];
            num += (1.f - g) * (1.f - g);
            cnt += 1.f;
        }
    }
    rn[t] = num; rc[t] = cnt;
    __syncthreads();
    for (int st = 128; st > 0; st >>= 1) {
        if (t < st) { rn[t] += rn[t + st]; rc[t] += rc[t + st]; }
        __syncthreads();
    }
    if (t == 0) out[0] = rc[0] > 0.f ? rn[0] / fmaxf(rc[0], 1.f) : 0.f;
}

// ---------------- host side ----------------
static void gemm(const float* A, const float* B, const float* bias, const float* resid,
                 float* C, int Mm, int Nn, int Kk, int b_nt, int act) {
    dim3 grid((Nn + 127) / 128, Mm / 128, 1);
    k_gemm<<<grid, 256, GEMM_SMEM>>>(A, B, bias, resid, C, Mm, Nn, Kk, b_nt, act, Kk);
}
static void gemm_splitk(const float* A, const float* B, const float* bias,
                        const float* resid, float* P, float* C,
                        int Mm, int Nn, int Kk, int b_nt, int nseg) {
    dim3 grid((Nn + 127) / 128, Mm / 128, nseg);
    k_gemm<<<grid, 256, GEMM_SMEM>>>(A, B, nullptr, nullptr, P, Mm, Nn, Kk, b_nt, 0, Kk / nseg);
    int total = Mm * Nn;
    k_sreduce<<<(total + 255) / 256, 256>>>(P, bias, resid, C, Nn, total, nseg);
}

extern "C" void kernel_launch(void* const* d_in, const int* in_sizes, int n_in,
                              void* d_out, int out_size) {
    const int*   tokens    = (const int*)d_in[0];
    const float* embed     = (const float*)d_in[1];
    const float* qkv_w     = (const float*)d_in[2];
    const float* qkv_b     = (const float*)d_in[3];
    const float* proj_w    = (const float*)d_in[4];
    const float* proj_b    = (const float*)d_in[5];
    const float* ln1_w     = (const float*)d_in[6];
    const float* mlp_w1    = (const float*)d_in[7];
    const float* mlp_b1    = (const float*)d_in[8];
    const float* mlp_w2    = (const float*)d_in[9];
    const float* mlp_b2    = (const float*)d_in[10];
    const float* ln2_w     = (const float*)d_in[11];
    const float* sal_w     = (const float*)d_in[12];
    const float* sal_b     = (const float*)d_in[13];
    const float* unc_w     = (const float*)d_in[14];
    const float* unc_b     = (const float*)d_in[15];
    const float* wg_w      = (const float*)d_in[16];
    const float* wg_b      = (const float*)d_in[17];
    const float* memproj_w = (const float*)d_in[18];
    const float* memproj_b = (const float*)d_in[19];
    const float* mem_k     = (const float*)d_in[20];
    const float* mem_v     = (const float*)d_in[21];
    float* out = (float*)d_out;

    static int smem_set = 0;
    if (!smem_set) {
        cudaFuncSetAttribute(k_gemm, cudaFuncAttributeMaxDynamicSharedMemorySize, GEMM_SMEM);
        smem_set = 1;
    }

    float *x, *xn, *qkv, *o, *h1, *kn, *res, *ret, *xout, *split, *need, *sal, *gate;
    cudaGetSymbolAddress((void**)&x, g_x);
    cudaGetSymbolAddress((void**)&xn, g_xn);
    cudaGetSymbolAddress((void**)&qkv, g_qkv);
    cudaGetSymbolAddress((void**)&o, g_o);
    cudaGetSymbolAddress((void**)&h1, g_h1);
    cudaGetSymbolAddress((void**)&kn, g_kn);
    cudaGetSymbolAddress((void**)&res, g_res);
    cudaGetSymbolAddress((void**)&ret, g_ret);
    cudaGetSymbolAddress((void**)&xout, g_xout);
    cudaGetSymbolAddress((void**)&split, g_split);
    cudaGetSymbolAddress((void**)&need, g_need);
    cudaGetSymbolAddress((void**)&sal, g_sal);
    cudaGetSymbolAddress((void**)&gate, g_gate);

    k_embed<<<(LQ * DM) / 256, 256>>>(tokens, embed, x);
    k_knorm<<<MMEM, 256>>>(mem_k, kn);

    for (int li = 0; li < NLAYER; li++) {
        k_rmsnorm<<<LQ, 256>>>(x, ln1_w + li * DM, xn);
        gemm(xn, qkv_w + (size_t)li * 3 * DM * DM, qkv_b + li * 3 * DM, nullptr,
             qkv, LQ, 3 * DM, DM, 1, 0);
        k_rope<<<LQ, 128>>>(qkv);
        {
            dim3 grid(LQ, NH);
            k_attn<<<grid, 128>>>(qkv, o);
        }
        gemm(o, proj_w + (size_t)li * DM * DM, proj_b + li * DM, x,
             x, LQ, DM, DM, 1, 0);
        k_rmsnorm<<<LQ, 256>>>(x, ln2_w + li * DM, xn);
        gemm(xn, mlp_w1 + (size_t)li * DFF * DM, mlp_b1 + li * DFF, nullptr,
             h1, LQ, DFF, DM, 1, 1);
        gemm_splitk(h1, mlp_w2 + (size_t)li * DM * DFF, mlp_b2 + li * DM, x,
                    split, x, LQ, DM, DFF, 1, 4);
    }

    // landmark memory read
    k_rowstats<<<LQ, 256>>>(x, unc_w, unc_b, sal_w, sal_b, wg_w, wg_b,
                            xn, need, sal, gate);
    gemm(xn, kn, nullptr, nullptr, res, LQ, MMEM, DM, 1, 0);
    k_softmax_mem<<<LQ, 256>>>(res);
    gemm_splitk(res, mem_v, nullptr, nullptr, split, ret, LQ, DM, MMEM, 0, 8);
    k_need<<<(LQ * DM) / 256, 256>>>(ret, need);
    gemm(ret, memproj_w, memproj_b, x, xout, LQ, DM, DM, 1, 0);

    // tied-head logits
    gemm(xout, embed, nullptr, nullptr, out, LQ, VOCAB, DM, 1, 0);

    if (out_size > LQ * VOCAB)
        k_penalty<<<1, 256>>>(sal, gate, out + (size_t)LQ * VOCAB);
}

// round 7
// speedup vs baseline: 2.2943x; 1.6415x over previous
#include <cuda_runtime.h>
#include <math.h>
#include <stdint.h>

#define LQ 2048
#define DM 256
#define NH 4
#define HDIM 64
#define NLAYER 6
#define MMEM 8192
#define VOCAB 50257
#define DFF 1024

// ---------------- scratch (device globals: allocation-free) ----------------
__device__ float g_x[LQ * DM];
__device__ float g_xn[LQ * DM];
__device__ float g_qkv[LQ * 3 * DM];
__device__ float g_o[LQ * DM];
__device__ float g_h1[LQ * DFF];
__device__ float g_kn[MMEM * DM];
__device__ float g_res[(size_t)LQ * MMEM];   // 64 MB resonance scores
__device__ float g_ret[LQ * DM];
__device__ float g_xout[LQ * DM];
__device__ float g_split[8 * LQ * DM];       // split-K partials (16 MB max)
__device__ float g_need[LQ];
__device__ float g_sal[LQ];
__device__ float g_gate[LQ];
// flash-attention partials: [NH][4 chunks][LQ][HDIM]
__device__ float g_pacc[NH * 4 * LQ * HDIM];
__device__ float g_pm[NH * 4 * LQ];
__device__ float g_pl[NH * 4 * LQ];

__device__ __forceinline__ uint32_t f2tf32(float f) {
    uint32_t u;
    asm("cvt.rna.tf32.f32 %0, %1;" : "=r"(u) : "f"(f));
    return u;
}
__device__ __forceinline__ void tf32_split(float f, uint32_t& b, uint32_t& s) {
    b = f2tf32(f);
    s = f2tf32(f - __uint_as_float(b));
}
__device__ __forceinline__ void cp16(float* dst, const float* src, bool ok) {
    uint32_t sa = (uint32_t)__cvta_generic_to_shared(dst);
    int sz = ok ? 16 : 0;
    asm volatile("cp.async.ca.shared.global [%0], [%1], 16, %2;\n"
                 :: "r"(sa), "l"(src), "r"(sz));
}

// ---------------- embedding lookup ----------------
__global__ void k_embed(const int* __restrict__ tokens, const float* __restrict__ embed,
                        float* __restrict__ x) {
    int idx = blockIdx.x * 256 + threadIdx.x;
    int l = idx >> 8, d = idx & 255;
    x[idx] = embed[(size_t)tokens[l] * DM + d];
}

// ---------------- rmsnorm ----------------
__global__ void k_rmsnorm(const float* __restrict__ x, const float* __restrict__ w,
                          float* __restrict__ xn) {
    int l = blockIdx.x, t = threadIdx.x;
    __shared__ float red[256];
    float v = x[l * DM + t];
    red[t] = v * v;
    __syncthreads();
    for (int s = 128; s > 0; s >>= 1) {
        if (t < s) red[t] += red[t + s];
        __syncthreads();
    }
    float r = rsqrtf(red[0] / (float)DM + 1e-6f);
    xn[l * DM + t] = v * r * w[t];
}

// ---------------- tf32x3 pipelined GEMM (identical to R4) ----------------
#define ASTRIDE 36
#define BSTRIDE 132
#define STG 4608
#define GEMM_SMEM (4 * STG * 4)
__global__ void __launch_bounds__(256)
k_gemm(const float* __restrict__ A, const float* __restrict__ B,
       const float* __restrict__ bias, const float* __restrict__ resid,
       float* __restrict__ C, int Mm, int Nn, int Kk,
       int b_nt, int act, int kseg) {
    extern __shared__ float smem[];
    float* As = smem;
    float* Bs = smem + 2 * STG;

    const int n0 = blockIdx.x * 128, m0 = blockIdx.y * 128;
    const int tid = threadIdx.x;
    const int w = tid >> 5, lane = tid & 31;
    const int g = lane >> 2, l4 = lane & 3;
    const int warp_m = (w >> 2) * 64;
    const int warp_n = (w & 3) * 32;
    const int kbeg = blockIdx.z * kseg;
    const int kend = kbeg + kseg;

    float acc[4][4][4];
#pragma unroll
    for (int i = 0; i < 4; i++)
#pragma unroll
        for (int j = 0; j < 4; j++)
#pragma unroll
            for (int r = 0; r < 4; r++) acc[i][j][r] = 0.f;

    auto load_tiles = [&](int k0, int st) {
        {
            int row = tid >> 1, colb = (tid & 1) * 16;
            const float* src = A + (size_t)(m0 + row) * Kk + k0 + colb;
            float* dst = As + st * STG + row * ASTRIDE + colb;
#pragma unroll
            for (int i = 0; i < 4; i++) cp16(dst + i * 4, src + i * 4, true);
        }
        if (b_nt) {
            int row = tid >> 1, colb = (tid & 1) * 16;
            int gn = n0 + row;
            bool ok = gn < Nn;
            const float* src = B + (size_t)(ok ? gn : 0) * Kk + k0 + colb;
            float* dst = Bs + st * STG + row * ASTRIDE + colb;
#pragma unroll
            for (int i = 0; i < 4; i++) cp16(dst + i * 4, src + i * 4, ok);
        } else {
            int k = tid >> 3, colb = (tid & 7) * 16;
            const float* src = B + (size_t)(k0 + k) * Nn + n0 + colb;
            float* dst = Bs + st * STG + k * BSTRIDE + colb;
#pragma unroll
            for (int i = 0; i < 4; i++) cp16(dst + i * 4, src + i * 4, true);
        }
        asm volatile("cp.async.commit_group;\n");
    };

    load_tiles(kbeg, 0);
    int stage = 0;
    for (int k0 = kbeg; k0 < kend; k0 += 32) {
        bool more = (k0 + 32) < kend;
        if (more) {
            load_tiles(k0 + 32, stage ^ 1);
            asm volatile("cp.async.wait_group 1;\n");
        } else {
            asm volatile("cp.async.wait_group 0;\n");
        }
        __syncthreads();

        const float* Af = As + stage * STG;
        const float* Bf = Bs + stage * STG;
#pragma unroll
        for (int ks = 0; ks < 4; ks++) {
            const int kc = ks * 8;
            uint32_t ab[4][4], ax[4][4];
#pragma unroll
            for (int mt = 0; mt < 4; mt++) {
                int r = (warp_m + mt * 16 + g) * ASTRIDE + kc + l4;
                tf32_split(Af[r],                   ab[mt][0], ax[mt][0]);
                tf32_split(Af[r + 8 * ASTRIDE],     ab[mt][1], ax[mt][1]);
                tf32_split(Af[r + 4],               ab[mt][2], ax[mt][2]);
                tf32_split(Af[r + 8 * ASTRIDE + 4], ab[mt][3], ax[mt][3]);
            }
            uint32_t bb[4][2], bx[4][2];
            if (b_nt) {
#pragma unroll
                for (int nt = 0; nt < 4; nt++) {
                    int r = (warp_n + nt * 8 + g) * ASTRIDE + kc + l4;
                    tf32_split(Bf[r],     bb[nt][0], bx[nt][0]);
                    tf32_split(Bf[r + 4], bb[nt][1], bx[nt][1]);
                }
            } else {
#pragma unroll
                for (int nt = 0; nt < 4; nt++) {
                    int cn = warp_n + nt * 8 + g;
                    tf32_split(Bf[(kc + l4) * BSTRIDE + cn],     bb[nt][0], bx[nt][0]);
                    tf32_split(Bf[(kc + l4 + 4) * BSTRIDE + cn], bb[nt][1], bx[nt][1]);
                }
            }
#define MMA(c, A0, A1, A2, A3, B0, B1)                                        \
    asm volatile("mma.sync.aligned.m16n8k8.row.col.f32.tf32.tf32.f32 "        \
                 "{%0,%1,%2,%3}, {%4,%5,%6,%7}, {%8,%9}, {%0,%1,%2,%3};\n"    \
                 : "+f"(c[0]), "+f"(c[1]), "+f"(c[2]), "+f"(c[3])             \
                 : "r"(A0), "r"(A1), "r"(A2), "r"(A3), "r"(B0), "r"(B1))
#pragma unroll
            for (int mt = 0; mt < 4; mt++)
#pragma unroll
                for (int nt = 0; nt < 4; nt++)
                    MMA(acc[mt][nt], ab[mt][0], ab[mt][1], ab[mt][2], ab[mt][3],
                        bb[nt][0], bb[nt][1]);
#pragma unroll
            for (int mt = 0; mt < 4; mt++)
#pragma unroll
                for (int nt = 0; nt < 4; nt++)
                    MMA(acc[mt][nt], ab[mt][0], ab[mt][1], ab[mt][2], ab[mt][3],
                        bx[nt][0], bx[nt][1]);
#pragma unroll
            for (int mt = 0; mt < 4; mt++)
#pragma unroll
                for (int nt = 0; nt < 4; nt++)
                    MMA(acc[mt][nt], ax[mt][0], ax[mt][1], ax[mt][2], ax[mt][3],
                        bb[nt][0], bb[nt][1]);
#undef MMA
        }
        __syncthreads();
        stage ^= 1;
    }

    bool partial = (gridDim.z > 1);
    float* Cw = partial ? C + (size_t)blockIdx.z * Mm * Nn : C;
#pragma unroll
    for (int mt = 0; mt < 4; mt++) {
#pragma unroll
        for (int nt = 0; nt < 4; nt++) {
#pragma unroll
            for (int half = 0; half < 2; half++) {
                int m = m0 + warp_m + mt * 16 + g + half * 8;
#pragma unroll
                for (int cc = 0; cc < 2; cc++) {
                    int n = n0 + warp_n + nt * 8 + l4 * 2 + cc;
                    if (n < Nn) {
                        float c = acc[mt][nt][half * 2 + cc];
                        if (!partial) {
                            if (bias) c += bias[n];
                            if (resid) c += resid[(size_t)m * Nn + n];
                            if (act == 1) c = 0.5f * c * (1.0f + erff(c * 0.70710678118654752f));
                        }
                        Cw[(size_t)m * Nn + n] = c;
                    }
                }
            }
        }
    }
}

// ---------------- split-K reduction ----------------
__global__ void k_sreduce(const float* __restrict__ P, const float* __restrict__ bias,
                          const float* __restrict__ resid, float* __restrict__ C,
                          int Nn, int total, int nseg) {
    int idx = blockIdx.x * 256 + threadIdx.x;
    if (idx >= total) return;
    float s = 0.f;
    for (int z = 0; z < nseg; z++) s += P[(size_t)z * total + idx];
    int n = idx % Nn;
    if (bias) s += bias[n];
    if (resid) s += resid[idx];
    C[idx] = s;
}

// ---------------- RoPE ----------------
__global__ void k_rope(float* __restrict__ qkv) {
    int l = blockIdx.x, t = threadIdx.x;
    int h = t >> 5, i = t & 31;
    float inv = (float)pow(10000.0, -(double)(2 * i) / (double)HDIM);
    float ang = (float)l * inv;
    float s, c;
    sincosf(ang, &s, &c);
    float* qp = qkv + (size_t)l * 768 + h * HDIM + 2 * i;
    float q0 = qp[0], q1 = qp[1];
    qp[0] = q0 * c - q1 * s;
    qp[1] = q0 * s + q1 * c;
    float* kp = qp + DM;
    float k0 = kp[0], k1 = kp[1];
    kp[0] = k0 * c - k1 * s;
    kp[1] = k0 * s + k1 * c;
}

// ---------------- flash attention partials ----------------
// CTA = (query block of 64, head, key-chunk of up to 8 key-tiles of 64).
// grid.x = 80 (sum over 32 qblocks of (qb>>3)+1), grid.y = head.
#define ASTR 72
#define ATTN_SMEM (4 * 64 * ASTR * 4)   // Qs,Ks,Vs,Ps = 73728B
__global__ void __launch_bounds__(256)
k_attn2(const float* __restrict__ qkv, float* __restrict__ pacc,
        float* __restrict__ pm, float* __restrict__ pl) {
    extern __shared__ float sf[];
    float* Qs = sf;
    float* Ks = sf + 64 * ASTR;
    float* Vs = sf + 2 * 64 * ASTR;
    float* Ps = sf + 3 * 64 * ASTR;

    int bx = blockIdx.x, h = blockIdx.y;
    int qb = 0, c = 0;
    {
        int accum = 0;
        for (int i = 0; i < 32; i++) {
            int nch = (i >> 3) + 1;
            if (bx < accum + nch) { qb = i; c = bx - accum; break; }
            accum += nch;
        }
    }
    const int q0 = qb * 64;
    const int tid = threadIdx.x;
    const int ty = tid >> 4, tx = tid & 15;
    const int lr = tid >> 2, lseg = (tid & 3) * 16;

    {   // load Q tile
        const float4* src = (const float4*)(qkv + (size_t)(q0 + lr) * 768 + h * HDIM + lseg);
        float4* dst = (float4*)(Qs + lr * ASTR + lseg);
#pragma unroll
        for (int i = 0; i < 4; i++) dst[i] = src[i];
    }

    float m_[4], l_[4], acc[4][4];
#pragma unroll
    for (int i = 0; i < 4; i++) {
        m_[i] = -INFINITY; l_[i] = 0.f;
#pragma unroll
        for (int j = 0; j < 4; j++) acc[i][j] = 0.f;
    }

    int t0 = c * 8, t1 = min(c * 8 + 8, qb + 1);
    for (int t = t0; t < t1; t++) {
        int k0 = t * 64;
        {
            const float4* sk = (const float4*)(qkv + (size_t)(k0 + lr) * 768 + DM + h * HDIM + lseg);
            const float4* sv = (const float4*)(qkv + (size_t)(k0 + lr) * 768 + 2 * DM + h * HDIM + lseg);
            float4* dk = (float4*)(Ks + lr * ASTR + lseg);
            float4* dv = (float4*)(Vs + lr * ASTR + lseg);
#pragma unroll
            for (int i = 0; i < 4; i++) { dk[i] = sk[i]; dv[i] = sv[i]; }
        }
        __syncthreads();

        float s[4][4] = {};
#pragma unroll
        for (int d4 = 0; d4 < HDIM; d4 += 4) {
            float4 q4[4], k4[4];
#pragma unroll
            for (int i = 0; i < 4; i++) q4[i] = *(const float4*)(Qs + (ty * 4 + i) * ASTR + d4);
#pragma unroll
            for (int j = 0; j < 4; j++) k4[j] = *(const float4*)(Ks + (tx * 4 + j) * ASTR + d4);
#pragma unroll
            for (int i = 0; i < 4; i++)
#pragma unroll
                for (int j = 0; j < 4; j++)
                    s[i][j] += q4[i].x * k4[j].x + q4[i].y * k4[j].y +
                               q4[i].z * k4[j].z + q4[i].w * k4[j].w;
        }
#pragma unroll
        for (int i = 0; i < 4; i++)
#pragma unroll
            for (int j = 0; j < 4; j++) {
                s[i][j] *= 0.125f;
                if (k0 + tx * 4 + j > q0 + ty * 4 + i) s[i][j] = -INFINITY;
            }
#pragma unroll
        for (int i = 0; i < 4; i++) {
            float mt = fmaxf(fmaxf(s[i][0], s[i][1]), fmaxf(s[i][2], s[i][3]));
#pragma unroll
            for (int sh = 8; sh > 0; sh >>= 1) mt = fmaxf(mt, __shfl_xor_sync(0xffffffffu, mt, sh));
            float mn = fmaxf(m_[i], mt);
            float alpha = expf(m_[i] - mn);
            float p0 = expf(s[i][0] - mn), p1 = expf(s[i][1] - mn);
            float p2 = expf(s[i][2] - mn), p3 = expf(s[i][3] - mn);
            float rs = p0 + p1 + p2 + p3;
#pragma unroll
            for (int sh = 8; sh > 0; sh >>= 1) rs += __shfl_xor_sync(0xffffffffu, rs, sh);
            l_[i] = l_[i] * alpha + rs;
            m_[i] = mn;
#pragma unroll
            for (int j = 0; j < 4; j++) acc[i][j] *= alpha;
            *(float4*)(Ps + (ty * 4 + i) * ASTR + tx * 4) = make_float4(p0, p1, p2, p3);
        }
        __syncthreads();
#pragma unroll
        for (int k4i = 0; k4i < 64; k4i += 4) {
            float4 pv[4], v4[4];
#pragma unroll
            for (int i = 0; i < 4; i++) pv[i] = *(const float4*)(Ps + (ty * 4 + i) * ASTR + k4i);
#pragma unroll
            for (int kk = 0; kk < 4; kk++) v4[kk] = *(const float4*)(Vs + (k4i + kk) * ASTR + tx * 4);
#pragma unroll
            for (int i = 0; i < 4; i++) {
                acc[i][0] += pv[i].x * v4[0].x + pv[i].y * v4[1].x + pv[i].z * v4[2].x + pv[i].w * v4[3].x;
                acc[i][1] += pv[i].x * v4[0].y + pv[i].y * v4[1].y + pv[i].z * v4[2].y + pv[i].w * v4[3].y;
                acc[i][2] += pv[i].x * v4[0].z + pv[i].y * v4[1].z + pv[i].z * v4[2].z + pv[i].w * v4[3].z;
                acc[i][3] += pv[i].x * v4[0].w + pv[i].y * v4[1].w + pv[i].z * v4[2].w + pv[i].w * v4[3].w;
            }
        }
        __syncthreads();
    }

    int base = (h * 4 + c) * LQ;
#pragma unroll
    for (int i = 0; i < 4; i++) {
        int q = q0 + ty * 4 + i;
        if (tx == 0) { pm[base + q] = m_[i]; pl[base + q] = l_[i]; }
        *(float4*)(pacc + ((size_t)(base + q)) * HDIM + tx * 4) =
            make_float4(acc[i][0], acc[i][1], acc[i][2], acc[i][3]);
    }
}

// ---------------- combine attention partials -> o (float) ----------------
__global__ void k_attn_comb(const float* __restrict__ pacc, const float* __restrict__ pm,
                            const float* __restrict__ pl, float* __restrict__ o) {
    int q = blockIdx.x, h = blockIdx.y, d = threadIdx.x;   // 64 threads
    int nch = ((q >> 6) >> 3) + 1;
    float M = -INFINITY;
    for (int c = 0; c < nch; c++) M = fmaxf(M, pm[(h * 4 + c) * LQ + q]);
    float L = 0.f, A = 0.f;
    for (int c = 0; c < nch; c++) {
        float wgt = expf(pm[(h * 4 + c) * LQ + q] - M);
        L += pl[(h * 4 + c) * LQ + q] * wgt;
        A += pacc[((size_t)((h * 4 + c) * LQ + q)) * HDIM + d] * wgt;
    }
    o[(size_t)q * DM + h * HDIM + d] = A / L;
}

// ---------------- row stats ----------------
__global__ void k_rowstats(const float* __restrict__ x,
                           const float* __restrict__ unc_w, const float* __restrict__ unc_b,
                           const float* __restrict__ sal_w, const float* __restrict__ sal_b,
                           const float* __restrict__ wg_w, const float* __restrict__ wg_b,
                           float* __restrict__ qn, float* __restrict__ need,
                           float* __restrict__ sal, float* __restrict__ gate) {
    int l = blockIdx.x, t = threadIdx.x;
    __shared__ float r0[256], r1[256], r2[256], r3[256];
    float v = x[l * DM + t];
    r0[t] = v * v;
    r1[t] = v * unc_w[t];
    r2[t] = v * sal_w[t];
    r3[t] = v * wg_w[t];
    __syncthreads();
    for (int s = 128; s > 0; s >>= 1) {
        if (t < s) { r0[t] += r0[t + s]; r1[t] += r1[t + s]; r2[t] += r2[t + s]; r3[t] += r3[t + s]; }
        __syncthreads();
    }
    float norm = sqrtf(r0[0]);
    qn[l * DM + t] = v / fmaxf(norm, 1e-12f);
    if (t == 0) {
        need[l] = 1.f / (1.f + expf(-(r1[0] + unc_b[0])));
        sal[l]  = 1.f / (1.f + expf(-(r2[0] + sal_b[0])));
        gate[l] = 1.f / (1.f + expf(-(r3[0] + wg_b[0])));
    }
}

// ---------------- normalize memory keys ----------------
__global__ void k_knorm(const float* __restrict__ mk, float* __restrict__ kn) {
    int m = blockIdx.x, t = threadIdx.x;
    __shared__ float red[256];
    float v = mk[(size_t)m * DM + t];
    red[t] = v * v;
    __syncthreads();
    for (int s = 128; s > 0; s >>= 1) { if (t < s) red[t] += red[t + s]; __syncthreads(); }
    kn[(size_t)m * DM + t] = v / fmaxf(sqrtf(red[0]), 1e-12f);
}

// ---------------- row softmax over memory slots ----------------
__global__ void k_softmax_mem(float* __restrict__ res) {
    int l = blockIdx.x, t = threadIdx.x;
    __shared__ float red[256];
    float* row = res + (size_t)l * MMEM;
    float lm = -INFINITY;
    for (int m = t; m < MMEM; m += 256) lm = fmaxf(lm, row[m] * 5.0f);
    red[t] = lm; __syncthreads();
    for (int s = 128; s > 0; s >>= 1) { if (t < s) red[t] = fmaxf(red[t], red[t + s]); __syncthreads(); }
    float mx = red[0]; __syncthreads();
    float ls = 0.f;
    for (int m = t; m < MMEM; m += 256) { float p = expf(row[m] * 5.0f - mx); row[m] = p; ls += p; }
    red[t] = ls; __syncthreads();
    for (int s = 128; s > 0; s >>= 1) { if (t < s) red[t] += red[t + s]; __syncthreads(); }
    float inv = 1.f / red[0];
    __syncthreads();
    for (int m = t; m < MMEM; m += 256) row[m] *= inv;
}

// ---------------- retrieved *= need[l] ----------------
__global__ void k_need(float* __restrict__ ret, const float* __restrict__ need) {
    int idx = blockIdx.x * 256 + threadIdx.x;
    ret[idx] *= need[idx >> 8];
}

// ---------------- gate penalty ----------------
__global__ void k_penalty(const float* __restrict__ sal, const float* __restrict__ gate,
                          float* __restrict__ out) {
    __shared__ float s[LQ];
    __shared__ float rn[256], rc[256];
    int t = threadIdx.x;
    for (int l = t; l < LQ; l += 256) s[l] = sal[l];
    __syncthreads();
    float num = 0.f, cnt = 0.f;
    for (int l = t; l < LQ; l += 256) {
        float v = s[l];
        int j0 = l - 15 < 0 ? 0 : l - 15;
        int j1 = l + 15 > LQ - 1 ? LQ - 1 : l + 15;
        float mx = -INFINITY;
        for (int j = j0; j <= j1; j++) mx = fmaxf(mx, s[j]);
        if (v == mx && v > 0.15f) {
            float g = gate[l];
            num += (1.f - g) * (1.f - g);
            cnt += 1.f;
        }
    }
    rn[t] = num; rc[t] = cnt;
    __syncthreads();
    for (int st = 128; st > 0; st >>= 1) {
        if (t < st) { rn[t] += rn[t + st]; rc[t] += rc[t + st]; }
        __syncthreads();
    }
    if (t == 0) out[0] = rc[0] > 0.f ? rn[0] / fmaxf(rc[0], 1.f) : 0.f;
}

// ---------------- host side ----------------
static void gemm(const float* A, const float* B, const float* bias, const float* resid,
                 float* C, int Mm, int Nn, int Kk, int b_nt, int act) {
    dim3 grid((Nn + 127) / 128, Mm / 128, 1);
    k_gemm<<<grid, 256, GEMM_SMEM>>>(A, B, bias, resid, C, Mm, Nn, Kk, b_nt, act, Kk);
}
static void gemm_splitk(const float* A, const float* B, const float* bias,
                        const float* resid, float* P, float* C,
                        int Mm, int Nn, int Kk, int b_nt, int nseg) {
    dim3 grid((Nn + 127) / 128, Mm / 128, nseg);
    k_gemm<<<grid, 256, GEMM_SMEM>>>(A, B, nullptr, nullptr, P, Mm, Nn, Kk, b_nt, 0, Kk / nseg);
    int total = Mm * Nn;
    k_sreduce<<<(total + 255) / 256, 256>>>(P, bias, resid, C, Nn, total, nseg);
}

extern "C" void kernel_launch(void* const* d_in, const int* in_sizes, int n_in,
                              void* d_out, int out_size) {
    const int*   tokens    = (const int*)d_in[0];
    const float* embed     = (const float*)d_in[1];
    const float* qkv_w     = (const float*)d_in[2];
    const float* qkv_b     = (const float*)d_in[3];
    const float* proj_w    = (const float*)d_in[4];
    const float* proj_b    = (const float*)d_in[5];
    const float* ln1_w     = (const float*)d_in[6];
    const float* mlp_w1    = (const float*)d_in[7];
    const float* mlp_b1    = (const float*)d_in[8];
    const float* mlp_w2    = (const float*)d_in[9];
    const float* mlp_b2    = (const float*)d_in[10];
    const float* ln2_w     = (const float*)d_in[11];
    const float* sal_w     = (const float*)d_in[12];
    const float* sal_b     = (const float*)d_in[13];
    const float* unc_w     = (const float*)d_in[14];
    const float* unc_b     = (const float*)d_in[15];
    const float* wg_w      = (const float*)d_in[16];
    const float* wg_b      = (const float*)d_in[17];
    const float* memproj_w = (const float*)d_in[18];
    const float* memproj_b = (const float*)d_in[19];
    const float* mem_k     = (const float*)d_in[20];
    const float* mem_v     = (const float*)d_in[21];
    float* out = (float*)d_out;

    cudaFuncSetAttribute(k_gemm, cudaFuncAttributeMaxDynamicSharedMemorySize, GEMM_SMEM);
    cudaFuncSetAttribute(k_attn2, cudaFuncAttributeMaxDynamicSharedMemorySize, ATTN_SMEM);

    float *x, *xn, *qkv, *o, *h1, *kn, *res, *ret, *xout, *split, *need, *sal, *gate;
    float *pacc, *pm, *pl;
    cudaGetSymbolAddress((void**)&x, g_x);
    cudaGetSymbolAddress((void**)&xn, g_xn);
    cudaGetSymbolAddress((void**)&qkv, g_qkv);
    cudaGetSymbolAddress((void**)&o, g_o);
    cudaGetSymbolAddress((void**)&h1, g_h1);
    cudaGetSymbolAddress((void**)&kn, g_kn);
    cudaGetSymbolAddress((void**)&res, g_res);
    cudaGetSymbolAddress((void**)&ret, g_ret);
    cudaGetSymbolAddress((void**)&xout, g_xout);
    cudaGetSymbolAddress((void**)&split, g_split);
    cudaGetSymbolAddress((void**)&need, g_need);
    cudaGetSymbolAddress((void**)&sal, g_sal);
    cudaGetSymbolAddress((void**)&gate, g_gate);
    cudaGetSymbolAddress((void**)&pacc, g_pacc);
    cudaGetSymbolAddress((void**)&pm, g_pm);
    cudaGetSymbolAddress((void**)&pl, g_pl);

    k_embed<<<(LQ * DM) / 256, 256>>>(tokens, embed, x);
    k_knorm<<<MMEM, 256>>>(mem_k, kn);

    for (int li = 0; li < NLAYER; li++) {
        k_rmsnorm<<<LQ, 256>>>(x, ln1_w + li * DM, xn);
        gemm(xn, qkv_w + (size_t)li * 3 * DM * DM, qkv_b + li * 3 * DM, nullptr,
             qkv, LQ, 3 * DM, DM, 1, 0);
        k_rope<<<LQ, 128>>>(qkv);
        {
            dim3 g(80, NH);
            k_attn2<<<g, 256, ATTN_SMEM>>>(qkv, pacc, pm, pl);
            dim3 gc(LQ, NH);
            k_attn_comb<<<gc, 64>>>(pacc, pm, pl, o);
        }
        gemm(o, proj_w + (size_t)li * DM * DM, proj_b + li * DM, x,
             x, LQ, DM, DM, 1, 0);
        k_rmsnorm<<<LQ, 256>>>(x, ln2_w + li * DM, xn);
        gemm(xn, mlp_w1 + (size_t)li * DFF * DM, mlp_b1 + li * DFF, nullptr,
             h1, LQ, DFF, DM, 1, 1);
        gemm_splitk(h1, mlp_w2 + (size_t)li * DM * DFF, mlp_b2 + li * DM, x,
                    split, x, LQ, DM, DFF, 1, 4);
    }

    // landmark memory read
    k_rowstats<<<LQ, 256>>>(x, unc_w, unc_b, sal_w, sal_b, wg_w, wg_b,
                            xn, need, sal, gate);
    gemm(xn, kn, nullptr, nullptr, res, LQ, MMEM, DM, 1, 0);
    k_softmax_mem<<<LQ, 256>>>(res);
    gemm_splitk(res, mem_v, nullptr, nullptr, split, ret, LQ, DM, MMEM, 0, 8);
    k_need<<<(LQ * DM) / 256, 256>>>(ret, need);
    gemm(ret, memproj_w, memproj_b, x, xout, LQ, DM, DM, 1, 0);

    // tied-head logits
    gemm(xout, embed, nullptr, nullptr, out, LQ, VOCAB, DM, 1, 0);

    if (out_size > LQ * VOCAB)
        k_penalty<<<1, 256>>>(sal, gate, out + (size_t)LQ * VOCAB);
}

// round 8
// speedup vs baseline: 2.3698x; 1.0329x over previous
#include <cuda_runtime.h>
#include <math.h>
#include <stdint.h>

#define LQ 2048
#define DM 256
#define NH 4
#define HDIM 64
#define NLAYER 6
#define MMEM 8192
#define VOCAB 50257
#define DFF 1024

// ---------------- scratch (device globals: allocation-free) ----------------
__device__ float g_x[LQ * DM];
__device__ float g_xn[LQ * DM];
__device__ float g_qkv[LQ * 3 * DM];
__device__ float g_o[LQ * DM];
__device__ float g_h1[LQ * DFF];
__device__ float g_kn[MMEM * DM];
__device__ float g_res[(size_t)LQ * MMEM];   // 64 MB resonance scores
__device__ float g_ret[LQ * DM];
__device__ float g_xout[LQ * DM];
__device__ float g_split[8 * LQ * DM];       // split-K partials (16 MB)
__device__ float g_need[LQ];
__device__ float g_sal[LQ];
__device__ float g_gate[LQ];
// flash-attention partials: [NH][4 chunks][LQ][HDIM]
__device__ float g_pacc[NH * 4 * LQ * HDIM];
__device__ float g_pm[NH * 4 * LQ];
__device__ float g_pl[NH * 4 * LQ];

__device__ __forceinline__ uint32_t f2tf32(float f) {
    uint32_t u;
    asm("cvt.rna.tf32.f32 %0, %1;" : "=r"(u) : "f"(f));
    return u;
}
__device__ __forceinline__ void tf32_split(float f, uint32_t& b, uint32_t& s) {
    b = f2tf32(f);
    s = f2tf32(f - __uint_as_float(b));
}
__device__ __forceinline__ void cp16(float* dst, const float* src, bool ok) {
    uint32_t sa = (uint32_t)__cvta_generic_to_shared(dst);
    int sz = ok ? 16 : 0;
    asm volatile("cp.async.ca.shared.global [%0], [%1], 16, %2;\n"
                 :: "r"(sa), "l"(src), "r"(sz));
}

// ---------------- embedding lookup ----------------
__global__ void k_embed(const int* __restrict__ tokens, const float* __restrict__ embed,
                        float* __restrict__ x) {
    int idx = blockIdx.x * 256 + threadIdx.x;
    int l = idx >> 8, d = idx & 255;
    x[idx] = embed[(size_t)tokens[l] * DM + d];
}

// ---------------- rmsnorm ----------------
__global__ void k_rmsnorm(const float* __restrict__ x, const float* __restrict__ w,
                          float* __restrict__ xn) {
    int l = blockIdx.x, t = threadIdx.x;
    __shared__ float red[256];
    float v = x[l * DM + t];
    red[t] = v * v;
    __syncthreads();
    for (int s = 128; s > 0; s >>= 1) {
        if (t < s) red[t] += red[t + s];
        __syncthreads();
    }
    float r = rsqrtf(red[0] / (float)DM + 1e-6f);
    xn[l * DM + t] = v * r * w[t];
}

// ---------------- tf32x3 pipelined GEMM, K-chunk 16, 2 CTAs/SM ----------------
// C[M,N] = A[M,K] * op(B) (+bias,+resid,+gelu), fp32-accurate via 3xTF32.
// b_nt=1: B is [N,K] (C=A*B^T); b_nt=0: B is [K,N] (N must be multiple of 128).
#define ASTRIDE 20    // 128x16 tile rows padded to 20 floats
#define BSTRIDE 132   // 16x128 B tile (b_nt=0) rows padded to 132 floats
#define STG 2560      // floats per tile buffer (128*20 = 2560 >= 16*132 = 2112)
#define GEMM_SMEM (4 * STG * 4)   // 2 stages x (A + B) = 40960 B
__global__ void __launch_bounds__(256, 2)
k_gemm(const float* __restrict__ A, const float* __restrict__ B,
       const float* __restrict__ bias, const float* __restrict__ resid,
       float* __restrict__ C, int Mm, int Nn, int Kk,
       int b_nt, int act, int kseg) {
    extern __shared__ float smem[];
    float* As = smem;                // [2][STG]
    float* Bs = smem + 2 * STG;      // [2][STG]

    const int n0 = blockIdx.x * 128, m0 = blockIdx.y * 128;
    const int tid = threadIdx.x;
    const int w = tid >> 5, lane = tid & 31;
    const int g = lane >> 2, l4 = lane & 3;
    const int warp_m = (w >> 2) * 64;
    const int warp_n = (w & 3) * 32;
    const int kbeg = blockIdx.z * kseg;
    const int kend = kbeg + kseg;

    float acc[4][4][4];
#pragma unroll
    for (int i = 0; i < 4; i++)
#pragma unroll
        for (int j = 0; j < 4; j++)
#pragma unroll
            for (int r = 0; r < 4; r++) acc[i][j][r] = 0.f;

    auto load_tiles = [&](int k0, int st) {
        {   // A tile 128x16: 2 threads/row, 8 floats each
            int row = tid >> 1, colb = (tid & 1) * 8;
            const float* src = A + (size_t)(m0 + row) * Kk + k0 + colb;
            float* dst = As + st * STG + row * ASTRIDE + colb;
            cp16(dst, src, true);
            cp16(dst + 4, src + 4, true);
        }
        if (b_nt) {
            int row = tid >> 1, colb = (tid & 1) * 8;
            int gn = n0 + row;
            bool ok = gn < Nn;
            const float* src = B + (size_t)(ok ? gn : 0) * Kk + k0 + colb;
            float* dst = Bs + st * STG + row * ASTRIDE + colb;
            cp16(dst, src, ok);
            cp16(dst + 4, src + 4, ok);
        } else {   // B[K,N] transpose tile 16x128: 16 threads/row, 8 floats each
            int k = tid >> 4, colb = (tid & 15) * 8;
            const float* src = B + (size_t)(k0 + k) * Nn + n0 + colb;
            float* dst = Bs + st * STG + k * BSTRIDE + colb;
            cp16(dst, src, true);
            cp16(dst + 4, src + 4, true);
        }
        asm volatile("cp.async.commit_group;\n");
    };

    load_tiles(kbeg, 0);
    int stage = 0;
    for (int k0 = kbeg; k0 < kend; k0 += 16) {
        bool more = (k0 + 16) < kend;
        if (more) {
            load_tiles(k0 + 16, stage ^ 1);
            asm volatile("cp.async.wait_group 1;\n");
        } else {
            asm volatile("cp.async.wait_group 0;\n");
        }
        __syncthreads();

        const float* Af = As + stage * STG;
        const float* Bf = Bs + stage * STG;
#pragma unroll
        for (int ks = 0; ks < 2; ks++) {
            const int kc = ks * 8;
            uint32_t ab[4][4], ax[4][4];
#pragma unroll
            for (int mt = 0; mt < 4; mt++) {
                int r = (warp_m + mt * 16 + g) * ASTRIDE + kc + l4;
                tf32_split(Af[r],                   ab[mt][0], ax[mt][0]);
                tf32_split(Af[r + 8 * ASTRIDE],     ab[mt][1], ax[mt][1]);
                tf32_split(Af[r + 4],               ab[mt][2], ax[mt][2]);
                tf32_split(Af[r + 8 * ASTRIDE + 4], ab[mt][3], ax[mt][3]);
            }
            uint32_t bb[4][2], bx[4][2];
            if (b_nt) {
#pragma unroll
                for (int nt = 0; nt < 4; nt++) {
                    int r = (warp_n + nt * 8 + g) * ASTRIDE + kc + l4;
                    tf32_split(Bf[r],     bb[nt][0], bx[nt][0]);
                    tf32_split(Bf[r + 4], bb[nt][1], bx[nt][1]);
                }
            } else {
#pragma unroll
                for (int nt = 0; nt < 4; nt++) {
                    int cn = warp_n + nt * 8 + g;
                    tf32_split(Bf[(kc + l4) * BSTRIDE + cn],     bb[nt][0], bx[nt][0]);
                    tf32_split(Bf[(kc + l4 + 4) * BSTRIDE + cn], bb[nt][1], bx[nt][1]);
                }
            }
#define MMA(c, A0, A1, A2, A3, B0, B1)                                        \
    asm volatile("mma.sync.aligned.m16n8k8.row.col.f32.tf32.tf32.f32 "        \
                 "{%0,%1,%2,%3}, {%4,%5,%6,%7}, {%8,%9}, {%0,%1,%2,%3};\n"    \
                 : "+f"(c[0]), "+f"(c[1]), "+f"(c[2]), "+f"(c[3])             \
                 : "r"(A0), "r"(A1), "r"(A2), "r"(A3), "r"(B0), "r"(B1))
#pragma unroll
            for (int mt = 0; mt < 4; mt++)
#pragma unroll
                for (int nt = 0; nt < 4; nt++)
                    MMA(acc[mt][nt], ab[mt][0], ab[mt][1], ab[mt][2], ab[mt][3],
                        bb[nt][0], bb[nt][1]);
#pragma unroll
            for (int mt = 0; mt < 4; mt++)
#pragma unroll
                for (int nt = 0; nt < 4; nt++)
                    MMA(acc[mt][nt], ab[mt][0], ab[mt][1], ab[mt][2], ab[mt][3],
                        bx[nt][0], bx[nt][1]);
#pragma unroll
            for (int mt = 0; mt < 4; mt++)
#pragma unroll
                for (int nt = 0; nt < 4; nt++)
                    MMA(acc[mt][nt], ax[mt][0], ax[mt][1], ax[mt][2], ax[mt][3],
                        bb[nt][0], bb[nt][1]);
#undef MMA
        }
        __syncthreads();
        stage ^= 1;
    }

    bool partial = (gridDim.z > 1);
    float* Cw = partial ? C + (size_t)blockIdx.z * Mm * Nn : C;
#pragma unroll
    for (int mt = 0; mt < 4; mt++) {
#pragma unroll
        for (int nt = 0; nt < 4; nt++) {
#pragma unroll
            for (int half = 0; half < 2; half++) {
                int m = m0 + warp_m + mt * 16 + g + half * 8;
#pragma unroll
                for (int cc = 0; cc < 2; cc++) {
                    int n = n0 + warp_n + nt * 8 + l4 * 2 + cc;
                    if (n < Nn) {
                        float c = acc[mt][nt][half * 2 + cc];
                        if (!partial) {
                            if (bias) c += bias[n];
                            if (resid) c += resid[(size_t)m * Nn + n];
                            if (act == 1) c = 0.5f * c * (1.0f + erff(c * 0.70710678118654752f));
                        }
                        Cw[(size_t)m * Nn + n] = c;
                    }
                }
            }
        }
    }
}

// ---------------- split-K reduction ----------------
__global__ void k_sreduce(const float* __restrict__ P, const float* __restrict__ bias,
                          const float* __restrict__ resid, float* __restrict__ C,
                          int Nn, int total, int nseg) {
    int idx = blockIdx.x * 256 + threadIdx.x;
    if (idx >= total) return;
    float s = 0.f;
    for (int z = 0; z < nseg; z++) s += P[(size_t)z * total + idx];
    int n = idx % Nn;
    if (bias) s += bias[n];
    if (resid) s += resid[idx];
    C[idx] = s;
}

// ---------------- RoPE ----------------
__global__ void k_rope(float* __restrict__ qkv) {
    int l = blockIdx.x, t = threadIdx.x;
    int h = t >> 5, i = t & 31;
    float inv = (float)pow(10000.0, -(double)(2 * i) / (double)HDIM);
    float ang = (float)l * inv;
    float s, c;
    sincosf(ang, &s, &c);
    float* qp = qkv + (size_t)l * 768 + h * HDIM + 2 * i;
    float q0 = qp[0], q1 = qp[1];
    qp[0] = q0 * c - q1 * s;
    qp[1] = q0 * s + q1 * c;
    float* kp = qp + DM;
    float k0 = kp[0], k1 = kp[1];
    kp[0] = k0 * c - k1 * s;
    kp[1] = k0 * s + k1 * c;
}

// ---------------- flash attention partials ----------------
#define ASTR 72
#define ATTN_SMEM (4 * 64 * ASTR * 4)   // 73728B
__global__ void __launch_bounds__(256)
k_attn2(const float* __restrict__ qkv, float* __restrict__ pacc,
        float* __restrict__ pm, float* __restrict__ pl) {
    extern __shared__ float sf[];
    float* Qs = sf;
    float* Ks = sf + 64 * ASTR;
    float* Vs = sf + 2 * 64 * ASTR;
    float* Ps = sf + 3 * 64 * ASTR;

    int bx = blockIdx.x, h = blockIdx.y;
    int qb = 0, c = 0;
    {
        int accum = 0;
        for (int i = 0; i < 32; i++) {
            int nch = (i >> 3) + 1;
            if (bx < accum + nch) { qb = i; c = bx - accum; break; }
            accum += nch;
        }
    }
    const int q0 = qb * 64;
    const int tid = threadIdx.x;
    const int ty = tid >> 4, tx = tid & 15;
    const int lr = tid >> 2, lseg = (tid & 3) * 16;

    {
        const float4* src = (const float4*)(qkv + (size_t)(q0 + lr) * 768 + h * HDIM + lseg);
        float4* dst = (float4*)(Qs + lr * ASTR + lseg);
#pragma unroll
        for (int i = 0; i < 4; i++) dst[i] = src[i];
    }

    float m_[4], l_[4], acc[4][4];
#pragma unroll
    for (int i = 0; i < 4; i++) {
        m_[i] = -INFINITY; l_[i] = 0.f;
#pragma unroll
        for (int j = 0; j < 4; j++) acc[i][j] = 0.f;
    }

    int t0 = c * 8, t1 = min(c * 8 + 8, qb + 1);
    for (int t = t0; t < t1; t++) {
        int k0 = t * 64;
        {
            const float4* sk = (const float4*)(qkv + (size_t)(k0 + lr) * 768 + DM + h * HDIM + lseg);
            const float4* sv = (const float4*)(qkv + (size_t)(k0 + lr) * 768 + 2 * DM + h * HDIM + lseg);
            float4* dk = (float4*)(Ks + lr * ASTR + lseg);
            float4* dv = (float4*)(Vs + lr * ASTR + lseg);
#pragma unroll
            for (int i = 0; i < 4; i++) { dk[i] = sk[i]; dv[i] = sv[i]; }
        }
        __syncthreads();

        float s[4][4] = {};
#pragma unroll
        for (int d4 = 0; d4 < HDIM; d4 += 4) {
            float4 q4[4], k4[4];
#pragma unroll
            for (int i = 0; i < 4; i++) q4[i] = *(const float4*)(Qs + (ty * 4 + i) * ASTR + d4);
#pragma unroll
            for (int j = 0; j < 4; j++) k4[j] = *(const float4*)(Ks + (tx * 4 + j) * ASTR + d4);
#pragma unroll
            for (int i = 0; i < 4; i++)
#pragma unroll
                for (int j = 0; j < 4; j++)
                    s[i][j] += q4[i].x * k4[j].x + q4[i].y * k4[j].y +
                               q4[i].z * k4[j].z + q4[i].w * k4[j].w;
        }
#pragma unroll
        for (int i = 0; i < 4; i++)
#pragma unroll
            for (int j = 0; j < 4; j++) {
                s[i][j] *= 0.125f;
                if (k0 + tx * 4 + j > q0 + ty * 4 + i) s[i][j] = -INFINITY;
            }
#pragma unroll
        for (int i = 0; i < 4; i++) {
            float mt = fmaxf(fmaxf(s[i][0], s[i][1]), fmaxf(s[i][2], s[i][3]));
#pragma unroll
            for (int sh = 8; sh > 0; sh >>= 1) mt = fmaxf(mt, __shfl_xor_sync(0xffffffffu, mt, sh));
            float mn = fmaxf(m_[i], mt);
            float alpha = expf(m_[i] - mn);
            float p0 = expf(s[i][0] - mn), p1 = expf(s[i][1] - mn);
            float p2 = expf(s[i][2] - mn), p3 = expf(s[i][3] - mn);
            float rs = p0 + p1 + p2 + p3;
#pragma unroll
            for (int sh = 8; sh > 0; sh >>= 1) rs += __shfl_xor_sync(0xffffffffu, rs, sh);
            l_[i] = l_[i] * alpha + rs;
            m_[i] = mn;
#pragma unroll
            for (int j = 0; j < 4; j++) acc[i][j] *= alpha;
            *(float4*)(Ps + (ty * 4 + i) * ASTR + tx * 4) = make_float4(p0, p1, p2, p3);
        }
        __syncthreads();
#pragma unroll
        for (int k4i = 0; k4i < 64; k4i += 4) {
            float4 pv[4], v4[4];
#pragma unroll
            for (int i = 0; i < 4; i++) pv[i] = *(const float4*)(Ps + (ty * 4 + i) * ASTR + k4i);
#pragma unroll
            for (int kk = 0; kk < 4; kk++) v4[kk] = *(const float4*)(Vs + (k4i + kk) * ASTR + tx * 4);
#pragma unroll
            for (int i = 0; i < 4; i++) {
                acc[i][0] += pv[i].x * v4[0].x + pv[i].y * v4[1].x + pv[i].z * v4[2].x + pv[i].w * v4[3].x;
                acc[i][1] += pv[i].x * v4[0].y + pv[i].y * v4[1].y + pv[i].z * v4[2].y + pv[i].w * v4[3].y;
                acc[i][2] += pv[i].x * v4[0].z + pv[i].y * v4[1].z + pv[i].z * v4[2].z + pv[i].w * v4[3].z;
                acc[i][3] += pv[i].x * v4[0].w + pv[i].y * v4[1].w + pv[i].z * v4[2].w + pv[i].w * v4[3].w;
            }
        }
        __syncthreads();
    }

    int base = (h * 4 + c) * LQ;
#pragma unroll
    for (int i = 0; i < 4; i++) {
        int q = q0 + ty * 4 + i;
        if (tx == 0) { pm[base + q] = m_[i]; pl[base + q] = l_[i]; }
        *(float4*)(pacc + ((size_t)(base + q)) * HDIM + tx * 4) =
            make_float4(acc[i][0], acc[i][1], acc[i][2], acc[i][3]);
    }
}

// ---------------- combine attention partials -> o ----------------
__global__ void k_attn_comb(const float* __restrict__ pacc, const float* __restrict__ pm,
                            const float* __restrict__ pl, float* __restrict__ o) {
    int q = blockIdx.x, h = blockIdx.y, d = threadIdx.x;
    int nch = ((q >> 6) >> 3) + 1;
    float M = -INFINITY;
    for (int c = 0; c < nch; c++) M = fmaxf(M, pm[(h * 4 + c) * LQ + q]);
    float L = 0.f, A = 0.f;
    for (int c = 0; c < nch; c++) {
        float wgt = expf(pm[(h * 4 + c) * LQ + q] - M);
        L += pl[(h * 4 + c) * LQ + q] * wgt;
        A += pacc[((size_t)((h * 4 + c) * LQ + q)) * HDIM + d] * wgt;
    }
    o[(size_t)q * DM + h * HDIM + d] = A / L;
}

// ---------------- row stats ----------------
__global__ void k_rowstats(const float* __restrict__ x,
                           const float* __restrict__ unc_w, const float* __restrict__ unc_b,
                           const float* __restrict__ sal_w, const float* __restrict__ sal_b,
                           const float* __restrict__ wg_w, const float* __restrict__ wg_b,
                           float* __restrict__ qn, float* __restrict__ need,
                           float* __restrict__ sal, float* __restrict__ gate) {
    int l = blockIdx.x, t = threadIdx.x;
    __shared__ float r0[256], r1[256], r2[256], r3[256];
    float v = x[l * DM + t];
    r0[t] = v * v;
    r1[t] = v * unc_w[t];
    r2[t] = v * sal_w[t];
    r3[t] = v * wg_w[t];
    __syncthreads();
    for (int s = 128; s > 0; s >>= 1) {
        if (t < s) { r0[t] += r0[t + s]; r1[t] += r1[t + s]; r2[t] += r2[t + s]; r3[t] += r3[t + s]; }
        __syncthreads();
    }
    float norm = sqrtf(r0[0]);
    qn[l * DM + t] = v / fmaxf(norm, 1e-12f);
    if (t == 0) {
        need[l] = 1.f / (1.f + expf(-(r1[0] + unc_b[0])));
        sal[l]  = 1.f / (1.f + expf(-(r2[0] + sal_b[0])));
        gate[l] = 1.f / (1.f + expf(-(r3[0] + wg_b[0])));
    }
}

// ---------------- normalize memory keys ----------------
__global__ void k_knorm(const float* __restrict__ mk, float* __restrict__ kn) {
    int m = blockIdx.x, t = threadIdx.x;
    __shared__ float red[256];
    float v = mk[(size_t)m * DM + t];
    red[t] = v * v;
    __syncthreads();
    for (int s = 128; s > 0; s >>= 1) { if (t < s) red[t] += red[t + s]; __syncthreads(); }
    kn[(size_t)m * DM + t] = v / fmaxf(sqrtf(red[0]), 1e-12f);
}

// ---------------- row softmax over memory slots ----------------
__global__ void k_softmax_mem(float* __restrict__ res) {
    int l = blockIdx.x, t = threadIdx.x;
    __shared__ float red[256];
    float* row = res + (size_t)l * MMEM;
    float lm = -INFINITY;
    for (int m = t; m < MMEM; m += 256) lm = fmaxf(lm, row[m] * 5.0f);
    red[t] = lm; __syncthreads();
    for (int s = 128; s > 0; s >>= 1) { if (t < s) red[t] = fmaxf(red[t], red[t + s]); __syncthreads(); }
    float mx = red[0]; __syncthreads();
    float ls = 0.f;
    for (int m = t; m < MMEM; m += 256) { float p = expf(row[m] * 5.0f - mx); row[m] = p; ls += p; }
    red[t] = ls; __syncthreads();
    for (int s = 128; s > 0; s >>= 1) { if (t < s) red[t] += red[t + s]; __syncthreads(); }
    float inv = 1.f / red[0];
    __syncthreads();
    for (int m = t; m < MMEM; m += 256) row[m] *= inv;
}

// ---------------- retrieved *= need[l] ----------------
__global__ void k_need(float* __restrict__ ret, const float* __restrict__ need) {
    int idx = blockIdx.x * 256 + threadIdx.x;
    ret[idx] *= need[idx >> 8];
}

// ---------------- gate penalty ----------------
__global__ void k_penalty(const float* __restrict__ sal, const float* __restrict__ gate,
                          float* __restrict__ out) {
    __shared__ float s[LQ];
    __shared__ float rn[256], rc[256];
    int t = threadIdx.x;
    for (int l = t; l < LQ; l += 256) s[l] = sal[l];
    __syncthreads();
    float num = 0.f, cnt = 0.f;
    for (int l = t; l < LQ; l += 256) {
        float v = s[l];
        int j0 = l - 15 < 0 ? 0 : l - 15;
        int j1 = l + 15 > LQ - 1 ? LQ - 1 : l + 15;
        float mx = -INFINITY;
        for (int j = j0; j <= j1; j++) mx = fmaxf(mx, s[j]);
        if (v == mx && v > 0.15f) {
            float g = gate[l];
            num += (1.f - g) * (1.f - g);
            cnt += 1.f;
        }
    }
    rn[t] = num; rc[t] = cnt;
    __syncthreads();
    for (int st = 128; st > 0; st >>= 1) {
        if (t < st) { rn[t] += rn[t + st]; rc[t] += rc[t + st]; }
        __syncthreads();
    }
    if (t == 0) out[0] = rc[0] > 0.f ? rn[0] / fmaxf(rc[0], 1.f) : 0.f;
}

// ---------------- host side ----------------
static void gemm(const float* A, const float* B, const float* bias, const float* resid,
                 float* C, int Mm, int Nn, int Kk, int b_nt, int act) {
    dim3 grid((Nn + 127) / 128, Mm / 128, 1);
    k_gemm<<<grid, 256, GEMM_SMEM>>>(A, B, bias, resid, C, Mm, Nn, Kk, b_nt, act, Kk);
}
static void gemm_splitk(const float* A, const float* B, const float* bias,
                        const float* resid, float* P, float* C,
                        int Mm, int Nn, int Kk, int b_nt, int nseg) {
    dim3 grid((Nn + 127) / 128, Mm / 128, nseg);
    k_gemm<<<grid, 256, GEMM_SMEM>>>(A, B, nullptr, nullptr, P, Mm, Nn, Kk, b_nt, 0, Kk / nseg);
    int total = Mm * Nn;
    k_sreduce<<<(total + 255) / 256, 256>>>(P, bias, resid, C, Nn, total, nseg);
}

extern "C" void kernel_launch(void* const* d_in, const int* in_sizes, int n_in,
                              void* d_out, int out_size) {
    const int*   tokens    = (const int*)d_in[0];
    const float* embed     = (const float*)d_in[1];
    const float* qkv_w     = (const float*)d_in[2];
    const float* qkv_b     = (const float*)d_in[3];
    const float* proj_w    = (const float*)d_in[4];
    const float* proj_b    = (const float*)d_in[5];
    const float* ln1_w     = (const float*)d_in[6];
    const float* mlp_w1    = (const float*)d_in[7];
    const float* mlp_b1    = (const float*)d_in[8];
    const float* mlp_w2    = (const float*)d_in[9];
    const float* mlp_b2    = (const float*)d_in[10];
    const float* ln2_w     = (const float*)d_in[11];
    const float* sal_w     = (const float*)d_in[12];
    const float* sal_b     = (const float*)d_in[13];
    const float* unc_w     = (const float*)d_in[14];
    const float* unc_b     = (const float*)d_in[15];
    const float* wg_w      = (const float*)d_in[16];
    const float* wg_b      = (const float*)d_in[17];
    const float* memproj_w = (const float*)d_in[18];
    const float* memproj_b = (const float*)d_in[19];
    const float* mem_k     = (const float*)d_in[20];
    const float* mem_v     = (const float*)d_in[21];
    float* out = (float*)d_out;

    cudaFuncSetAttribute(k_gemm, cudaFuncAttributeMaxDynamicSharedMemorySize, GEMM_SMEM);
    cudaFuncSetAttribute(k_attn2, cudaFuncAttributeMaxDynamicSharedMemorySize, ATTN_SMEM);

    float *x, *xn, *qkv, *o, *h1, *kn, *res, *ret, *xout, *split, *need, *sal, *gate;
    float *pacc, *pm, *pl;
    cudaGetSymbolAddress((void**)&x, g_x);
    cudaGetSymbolAddress((void**)&xn, g_xn);
    cudaGetSymbolAddress((void**)&qkv, g_qkv);
    cudaGetSymbolAddress((void**)&o, g_o);
    cudaGetSymbolAddress((void**)&h1, g_h1);
    cudaGetSymbolAddress((void**)&kn, g_kn);
    cudaGetSymbolAddress((void**)&res, g_res);
    cudaGetSymbolAddress((void**)&ret, g_ret);
    cudaGetSymbolAddress((void**)&xout, g_xout);
    cudaGetSymbolAddress((void**)&split, g_split);
    cudaGetSymbolAddress((void**)&need, g_need);
    cudaGetSymbolAddress((void**)&sal, g_sal);
    cudaGetSymbolAddress((void**)&gate, g_gate);
    cudaGetSymbolAddress((void**)&pacc, g_pacc);
    cudaGetSymbolAddress((void**)&pm, g_pm);
    cudaGetSymbolAddress((void**)&pl, g_pl);

    k_embed<<<(LQ * DM) / 256, 256>>>(tokens, embed, x);
    k_knorm<<<MMEM, 256>>>(mem_k, kn);

    for (int li = 0; li < NLAYER; li++) {
        k_rmsnorm<<<LQ, 256>>>(x, ln1_w + li * DM, xn);
        // qkv: 96 CTAs underfills -> split-K 2 (192 CTAs)
        gemm_splitk(xn, qkv_w + (size_t)li * 3 * DM * DM, qkv_b + li * 3 * DM, nullptr,
                    split, qkv, LQ, 3 * DM, DM, 1, 2);
        k_rope<<<LQ, 128>>>(qkv);
        {
            dim3 g(80, NH);
            k_attn2<<<g, 256, ATTN_SMEM>>>(qkv, pacc, pm, pl);
            dim3 gc(LQ, NH);
            k_attn_comb<<<gc, 64>>>(pacc, pm, pl, o);
        }
        // proj: 32 CTAs underfills -> split-K 4 (128 CTAs)
        gemm_splitk(o, proj_w + (size_t)li * DM * DM, proj_b + li * DM, x,
                    split, x, LQ, DM, DM, 1, 4);
        k_rmsnorm<<<LQ, 256>>>(x, ln2_w + li * DM, xn);
        gemm(xn, mlp_w1 + (size_t)li * DFF * DM, mlp_b1 + li * DFF, nullptr,
             h1, LQ, DFF, DM, 1, 1);
        gemm_splitk(h1, mlp_w2 + (size_t)li * DM * DFF, mlp_b2 + li * DM, x,
                    split, x, LQ, DM, DFF, 1, 4);
    }

    // landmark memory read
    k_rowstats<<<LQ, 256>>>(x, unc_w, unc_b, sal_w, sal_b, wg_w, wg_b,
                            xn, need, sal, gate);
    gemm(xn, kn, nullptr, nullptr, res, LQ, MMEM, DM, 1, 0);
    k_softmax_mem<<<LQ, 256>>>(res);
    gemm_splitk(res, mem_v, nullptr, nullptr, split, ret, LQ, DM, MMEM, 0, 8);
    k_need<<<(LQ * DM) / 256, 256>>>(ret, need);
    // memproj: 32 CTAs underfills -> split-K 4
    gemm_splitk(ret, memproj_w, memproj_b, x, split, xout, LQ, DM, DM, 1, 4);

    // tied-head logits
    gemm(xout, embed, nullptr, nullptr, out, LQ, VOCAB, DM, 1, 0);

    if (out_size > LQ * VOCAB)
        k_penalty<<<1, 256>>>(sal, gate, out + (size_t)LQ * VOCAB);
}

// round 9
// speedup vs baseline: 2.6305x; 1.1100x over previous
#include <cuda_runtime.h>
#include <math.h>
#include <stdint.h>

#define LQ 2048
#define DM 256
#define NH 4
#define HDIM 64
#define NLAYER 6
#define MMEM 8192
#define VOCAB 50257
#define DFF 1024

// ---------------- scratch (device globals: allocation-free) ----------------
__device__ float g_x[LQ * DM];
__device__ float g_xn[LQ * DM];
__device__ float g_qkv[LQ * 3 * DM];
__device__ float g_o[LQ * DM];
__device__ float g_h1[LQ * DFF];
__device__ float g_kn[MMEM * DM];
__device__ float g_res[(size_t)LQ * MMEM];   // 64 MB resonance scores
__device__ float g_ret[LQ * DM];
__device__ float g_xout[LQ * DM];
__device__ float g_split[4 * LQ * 768];      // split-K partials (24 MB; fits qkv nseg=4)
__device__ float g_need[LQ];
__device__ float g_sal[LQ];
__device__ float g_gate[LQ];
// flash-attention partials: [NH][4 chunks][LQ][HDIM]
__device__ float g_pacc[NH * 4 * LQ * HDIM];
__device__ float g_pm[NH * 4 * LQ];
__device__ float g_pl[NH * 4 * LQ];

__device__ __forceinline__ uint32_t f2tf32(float f) {
    uint32_t u;
    asm("cvt.rna.tf32.f32 %0, %1;" : "=r"(u) : "f"(f));
    return u;
}
__device__ __forceinline__ void tf32_split(float f, uint32_t& b, uint32_t& s) {
    b = f2tf32(f);
    s = f2tf32(f - __uint_as_float(b));
}
__device__ __forceinline__ void cp16(float* dst, const float* src, bool ok) {
    uint32_t sa = (uint32_t)__cvta_generic_to_shared(dst);
    int sz = ok ? 16 : 0;
    asm volatile("cp.async.ca.shared.global [%0], [%1], 16, %2;\n"
                 :: "r"(sa), "l"(src), "r"(sz));
}

// ---------------- embedding lookup ----------------
__global__ void k_embed(const int* __restrict__ tokens, const float* __restrict__ embed,
                        float* __restrict__ x) {
    int idx = blockIdx.x * 256 + threadIdx.x;
    int l = idx >> 8, d = idx & 255;
    x[idx] = embed[(size_t)tokens[l] * DM + d];
}

// ---------------- rmsnorm ----------------
__global__ void k_rmsnorm(const float* __restrict__ x, const float* __restrict__ w,
                          float* __restrict__ xn) {
    int l = blockIdx.x, t = threadIdx.x;
    __shared__ float red[256];
    float v = x[l * DM + t];
    red[t] = v * v;
    __syncthreads();
    for (int s = 128; s > 0; s >>= 1) {
        if (t < s) red[t] += red[t + s];
        __syncthreads();
    }
    float r = rsqrtf(red[0] / (float)DM + 1e-6f);
    xn[l * DM + t] = v * r * w[t];
}

// ---------------- tiered tf32 pipelined GEMM ----------------
// fast=0: tf32x3 (fp32-accurate). fast=1: single-pass tf32 (for GEMMs whose
// consumers tolerate ~5e-4 rel err: logits, ret).
// b_nt=1: B is [N,K] (C=A*B^T); b_nt=0: B is [K,N] (N multiple of 128).
#define ASTRIDE 20
#define BSTRIDE 132
#define STG 2560
#define GEMM_SMEM (4 * STG * 4)   // 40960 B
__global__ void __launch_bounds__(256, 2)
k_gemm(const float* __restrict__ A, const float* __restrict__ B,
       const float* __restrict__ bias, const float* __restrict__ resid,
       float* __restrict__ C, int Mm, int Nn, int Kk,
       int b_nt, int act, int kseg, int fast) {
    extern __shared__ float smem[];
    float* As = smem;
    float* Bs = smem + 2 * STG;

    const int n0 = blockIdx.x * 128, m0 = blockIdx.y * 128;
    const int tid = threadIdx.x;
    const int w = tid >> 5, lane = tid & 31;
    const int g = lane >> 2, l4 = lane & 3;
    const int warp_m = (w >> 2) * 64;
    const int warp_n = (w & 3) * 32;
    const int kbeg = blockIdx.z * kseg;
    const int kend = kbeg + kseg;

    float acc[4][4][4];
#pragma unroll
    for (int i = 0; i < 4; i++)
#pragma unroll
        for (int j = 0; j < 4; j++)
#pragma unroll
            for (int r = 0; r < 4; r++) acc[i][j][r] = 0.f;

    auto load_tiles = [&](int k0, int st) {
        {
            int row = tid >> 1, colb = (tid & 1) * 8;
            const float* src = A + (size_t)(m0 + row) * Kk + k0 + colb;
            float* dst = As + st * STG + row * ASTRIDE + colb;
            cp16(dst, src, true);
            cp16(dst + 4, src + 4, true);
        }
        if (b_nt) {
            int row = tid >> 1, colb = (tid & 1) * 8;
            int gn = n0 + row;
            bool ok = gn < Nn;
            const float* src = B + (size_t)(ok ? gn : 0) * Kk + k0 + colb;
            float* dst = Bs + st * STG + row * ASTRIDE + colb;
            cp16(dst, src, ok);
            cp16(dst + 4, src + 4, ok);
        } else {
            int k = tid >> 4, colb = (tid & 15) * 8;
            const float* src = B + (size_t)(k0 + k) * Nn + n0 + colb;
            float* dst = Bs + st * STG + k * BSTRIDE + colb;
            cp16(dst, src, true);
            cp16(dst + 4, src + 4, true);
        }
        asm volatile("cp.async.commit_group;\n");
    };

    load_tiles(kbeg, 0);
    int stage = 0;
    for (int k0 = kbeg; k0 < kend; k0 += 16) {
        bool more = (k0 + 16) < kend;
        if (more) {
            load_tiles(k0 + 16, stage ^ 1);
            asm volatile("cp.async.wait_group 1;\n");
        } else {
            asm volatile("cp.async.wait_group 0;\n");
        }
        __syncthreads();

        const float* Af = As + stage * STG;
        const float* Bf = Bs + stage * STG;
#pragma unroll
        for (int ks = 0; ks < 2; ks++) {
            const int kc = ks * 8;
            uint32_t ab[4][4], ax[4][4];
            uint32_t bb[4][2], bx[4][2];
            if (fast) {
#pragma unroll
                for (int mt = 0; mt < 4; mt++) {
                    int r = (warp_m + mt * 16 + g) * ASTRIDE + kc + l4;
                    ab[mt][0] = f2tf32(Af[r]);
                    ab[mt][1] = f2tf32(Af[r + 8 * ASTRIDE]);
                    ab[mt][2] = f2tf32(Af[r + 4]);
                    ab[mt][3] = f2tf32(Af[r + 8 * ASTRIDE + 4]);
                }
                if (b_nt) {
#pragma unroll
                    for (int nt = 0; nt < 4; nt++) {
                        int r = (warp_n + nt * 8 + g) * ASTRIDE + kc + l4;
                        bb[nt][0] = f2tf32(Bf[r]);
                        bb[nt][1] = f2tf32(Bf[r + 4]);
                    }
                } else {
#pragma unroll
                    for (int nt = 0; nt < 4; nt++) {
                        int cn = warp_n + nt * 8 + g;
                        bb[nt][0] = f2tf32(Bf[(kc + l4) * BSTRIDE + cn]);
                        bb[nt][1] = f2tf32(Bf[(kc + l4 + 4) * BSTRIDE + cn]);
                    }
                }
            } else {
#pragma unroll
                for (int mt = 0; mt < 4; mt++) {
                    int r = (warp_m + mt * 16 + g) * ASTRIDE + kc + l4;
                    tf32_split(Af[r],                   ab[mt][0], ax[mt][0]);
                    tf32_split(Af[r + 8 * ASTRIDE],     ab[mt][1], ax[mt][1]);
                    tf32_split(Af[r + 4],               ab[mt][2], ax[mt][2]);
                    tf32_split(Af[r + 8 * ASTRIDE + 4], ab[mt][3], ax[mt][3]);
                }
                if (b_nt) {
#pragma unroll
                    for (int nt = 0; nt < 4; nt++) {
                        int r = (warp_n + nt * 8 + g) * ASTRIDE + kc + l4;
                        tf32_split(Bf[r],     bb[nt][0], bx[nt][0]);
                        tf32_split(Bf[r + 4], bb[nt][1], bx[nt][1]);
                    }
                } else {
#pragma unroll
                    for (int nt = 0; nt < 4; nt++) {
                        int cn = warp_n + nt * 8 + g;
                        tf32_split(Bf[(kc + l4) * BSTRIDE + cn],     bb[nt][0], bx[nt][0]);
                        tf32_split(Bf[(kc + l4 + 4) * BSTRIDE + cn], bb[nt][1], bx[nt][1]);
                    }
                }
            }
#define MMA(c, A0, A1, A2, A3, B0, B1)                                        \
    asm volatile("mma.sync.aligned.m16n8k8.row.col.f32.tf32.tf32.f32 "        \
                 "{%0,%1,%2,%3}, {%4,%5,%6,%7}, {%8,%9}, {%0,%1,%2,%3};\n"    \
                 : "+f"(c[0]), "+f"(c[1]), "+f"(c[2]), "+f"(c[3])             \
                 : "r"(A0), "r"(A1), "r"(A2), "r"(A3), "r"(B0), "r"(B1))
#pragma unroll
            for (int mt = 0; mt < 4; mt++)
#pragma unroll
                for (int nt = 0; nt < 4; nt++)
                    MMA(acc[mt][nt], ab[mt][0], ab[mt][1], ab[mt][2], ab[mt][3],
                        bb[nt][0], bb[nt][1]);
            if (!fast) {
#pragma unroll
                for (int mt = 0; mt < 4; mt++)
#pragma unroll
                    for (int nt = 0; nt < 4; nt++)
                        MMA(acc[mt][nt], ab[mt][0], ab[mt][1], ab[mt][2], ab[mt][3],
                            bx[nt][0], bx[nt][1]);
#pragma unroll
                for (int mt = 0; mt < 4; mt++)
#pragma unroll
                    for (int nt = 0; nt < 4; nt++)
                        MMA(acc[mt][nt], ax[mt][0], ax[mt][1], ax[mt][2], ax[mt][3],
                            bb[nt][0], bb[nt][1]);
            }
#undef MMA
        }
        __syncthreads();
        stage ^= 1;
    }

    bool partial = (gridDim.z > 1);
    float* Cw = partial ? C + (size_t)blockIdx.z * Mm * Nn : C;
#pragma unroll
    for (int mt = 0; mt < 4; mt++) {
#pragma unroll
        for (int nt = 0; nt < 4; nt++) {
#pragma unroll
            for (int half = 0; half < 2; half++) {
                int m = m0 + warp_m + mt * 16 + g + half * 8;
#pragma unroll
                for (int cc = 0; cc < 2; cc++) {
                    int n = n0 + warp_n + nt * 8 + l4 * 2 + cc;
                    if (n < Nn) {
                        float c = acc[mt][nt][half * 2 + cc];
                        if (!partial) {
                            if (bias) c += bias[n];
                            if (resid) c += resid[(size_t)m * Nn + n];
                            if (act == 1) c = 0.5f * c * (1.0f + erff(c * 0.70710678118654752f));
                        }
                        Cw[(size_t)m * Nn + n] = c;
                    }
                }
            }
        }
    }
}

// ---------------- split-K reduction (with optional bias/resid/gelu) ----------------
__global__ void k_sreduce(const float* __restrict__ P, const float* __restrict__ bias,
                          const float* __restrict__ resid, float* __restrict__ C,
                          int Nn, int total, int nseg, int act) {
    int idx = blockIdx.x * 256 + threadIdx.x;
    if (idx >= total) return;
    float s = 0.f;
    for (int z = 0; z < nseg; z++) s += P[(size_t)z * total + idx];
    int n = idx % Nn;
    if (bias) s += bias[n];
    if (resid) s += resid[idx];
    if (act == 1) s = 0.5f * s * (1.0f + erff(s * 0.70710678118654752f));
    C[idx] = s;
}

// ---------------- RoPE ----------------
__global__ void k_rope(float* __restrict__ qkv) {
    int l = blockIdx.x, t = threadIdx.x;
    int h = t >> 5, i = t & 31;
    float inv = (float)pow(10000.0, -(double)(2 * i) / (double)HDIM);
    float ang = (float)l * inv;
    float s, c;
    sincosf(ang, &s, &c);
    float* qp = qkv + (size_t)l * 768 + h * HDIM + 2 * i;
    float q0 = qp[0], q1 = qp[1];
    qp[0] = q0 * c - q1 * s;
    qp[1] = q0 * s + q1 * c;
    float* kp = qp + DM;
    float k0 = kp[0], k1 = kp[1];
    kp[0] = k0 * c - k1 * s;
    kp[1] = k0 * s + k1 * c;
}

// ---------------- flash attention partials ----------------
#define ASTR 72
#define ATTN_SMEM (4 * 64 * ASTR * 4)
__global__ void __launch_bounds__(256)
k_attn2(const float* __restrict__ qkv, float* __restrict__ pacc,
        float* __restrict__ pm, float* __restrict__ pl) {
    extern __shared__ float sf[];
    float* Qs = sf;
    float* Ks = sf + 64 * ASTR;
    float* Vs = sf + 2 * 64 * ASTR;
    float* Ps = sf + 3 * 64 * ASTR;

    int bx = blockIdx.x, h = blockIdx.y;
    int qb = 0, c = 0;
    {
        int accum = 0;
        for (int i = 0; i < 32; i++) {
            int nch = (i >> 3) + 1;
            if (bx < accum + nch) { qb = i; c = bx - accum; break; }
            accum += nch;
        }
    }
    const int q0 = qb * 64;
    const int tid = threadIdx.x;
    const int ty = tid >> 4, tx = tid & 15;
    const int lr = tid >> 2, lseg = (tid & 3) * 16;

    {
        const float4* src = (const float4*)(qkv + (size_t)(q0 + lr) * 768 + h * HDIM + lseg);
        float4* dst = (float4*)(Qs + lr * ASTR + lseg);
#pragma unroll
        for (int i = 0; i < 4; i++) dst[i] = src[i];
    }

    float m_[4], l_[4], acc[4][4];
#pragma unroll
    for (int i = 0; i < 4; i++) {
        m_[i] = -INFINITY; l_[i] = 0.f;
#pragma unroll
        for (int j = 0; j < 4; j++) acc[i][j] = 0.f;
    }

    int t0 = c * 8, t1 = min(c * 8 + 8, qb + 1);
    for (int t = t0; t < t1; t++) {
        int k0 = t * 64;
        {
            const float4* sk = (const float4*)(qkv + (size_t)(k0 + lr) * 768 + DM + h * HDIM + lseg);
            const float4* sv = (const float4*)(qkv + (size_t)(k0 + lr) * 768 + 2 * DM + h * HDIM + lseg);
            float4* dk = (float4*)(Ks + lr * ASTR + lseg);
            float4* dv = (float4*)(Vs + lr * ASTR + lseg);
#pragma unroll
            for (int i = 0; i < 4; i++) { dk[i] = sk[i]; dv[i] = sv[i]; }
        }
        __syncthreads();

        float s[4][4] = {};
#pragma unroll
        for (int d4 = 0; d4 < HDIM; d4 += 4) {
            float4 q4[4], k4[4];
#pragma unroll
            for (int i = 0; i < 4; i++) q4[i] = *(const float4*)(Qs + (ty * 4 + i) * ASTR + d4);
#pragma unroll
            for (int j = 0; j < 4; j++) k4[j] = *(const float4*)(Ks + (tx * 4 + j) * ASTR + d4);
#pragma unroll
            for (int i = 0; i < 4; i++)
#pragma unroll
                for (int j = 0; j < 4; j++)
                    s[i][j] += q4[i].x * k4[j].x + q4[i].y * k4[j].y +
                               q4[i].z * k4[j].z + q4[i].w * k4[j].w;
        }
#pragma unroll
        for (int i = 0; i < 4; i++)
#pragma unroll
            for (int j = 0; j < 4; j++) {
                s[i][j] *= 0.125f;
                if (k0 + tx * 4 + j > q0 + ty * 4 + i) s[i][j] = -INFINITY;
            }
#pragma unroll
        for (int i = 0; i < 4; i++) {
            float mt = fmaxf(fmaxf(s[i][0], s[i][1]), fmaxf(s[i][2], s[i][3]));
#pragma unroll
            for (int sh = 8; sh > 0; sh >>= 1) mt = fmaxf(mt, __shfl_xor_sync(0xffffffffu, mt, sh));
            float mn = fmaxf(m_[i], mt);
            float alpha = expf(m_[i] - mn);
            float p0 = expf(s[i][0] - mn), p1 = expf(s[i][1] - mn);
            float p2 = expf(s[i][2] - mn), p3 = expf(s[i][3] - mn);
            float rs = p0 + p1 + p2 + p3;
#pragma unroll
            for (int sh = 8; sh > 0; sh >>= 1) rs += __shfl_xor_sync(0xffffffffu, rs, sh);
            l_[i] = l_[i] * alpha + rs;
            m_[i] = mn;
#pragma unroll
            for (int j = 0; j < 4; j++) acc[i][j] *= alpha;
            *(float4*)(Ps + (ty * 4 + i) * ASTR + tx * 4) = make_float4(p0, p1, p2, p3);
        }
        __syncthreads();
#pragma unroll
        for (int k4i = 0; k4i < 64; k4i += 4) {
            float4 pv[4], v4[4];
#pragma unroll
            for (int i = 0; i < 4; i++) pv[i] = *(const float4*)(Ps + (ty * 4 + i) * ASTR + k4i);
#pragma unroll
            for (int kk = 0; kk < 4; kk++) v4[kk] = *(const float4*)(Vs + (k4i + kk) * ASTR + tx * 4);
#pragma unroll
            for (int i = 0; i < 4; i++) {
                acc[i][0] += pv[i].x * v4[0].x + pv[i].y * v4[1].x + pv[i].z * v4[2].x + pv[i].w * v4[3].x;
                acc[i][1] += pv[i].x * v4[0].y + pv[i].y * v4[1].y + pv[i].z * v4[2].y + pv[i].w * v4[3].y;
                acc[i][2] += pv[i].x * v4[0].z + pv[i].y * v4[1].z + pv[i].z * v4[2].z + pv[i].w * v4[3].z;
                acc[i][3] += pv[i].x * v4[0].w + pv[i].y * v4[1].w + pv[i].z * v4[2].w + pv[i].w * v4[3].w;
            }
        }
        __syncthreads();
    }

    int base = (h * 4 + c) * LQ;
#pragma unroll
    for (int i = 0; i < 4; i++) {
        int q = q0 + ty * 4 + i;
        if (tx == 0) { pm[base + q] = m_[i]; pl[base + q] = l_[i]; }
        *(float4*)(pacc + ((size_t)(base + q)) * HDIM + tx * 4) =
            make_float4(acc[i][0], acc[i][1], acc[i][2], acc[i][3]);
    }
}

// ---------------- combine attention partials -> o ----------------
__global__ void k_attn_comb(const float* __restrict__ pacc, const float* __restrict__ pm,
                            const float* __restrict__ pl, float* __restrict__ o) {
    int q = blockIdx.x, h = blockIdx.y, d = threadIdx.x;
    int nch = ((q >> 6) >> 3) + 1;
    float M = -INFINITY;
    for (int c = 0; c < nch; c++) M = fmaxf(M, pm[(h * 4 + c) * LQ + q]);
    float L = 0.f, A = 0.f;
    for (int c = 0; c < nch; c++) {
        float wgt = expf(pm[(h * 4 + c) * LQ + q] - M);
        L += pl[(h * 4 + c) * LQ + q] * wgt;
        A += pacc[((size_t)((h * 4 + c) * LQ + q)) * HDIM + d] * wgt;
    }
    o[(size_t)q * DM + h * HDIM + d] = A / L;
}

// ---------------- row stats ----------------
__global__ void k_rowstats(const float* __restrict__ x,
                           const float* __restrict__ unc_w, const float* __restrict__ unc_b,
                           const float* __restrict__ sal_w, const float* __restrict__ sal_b,
                           const float* __restrict__ wg_w, const float* __restrict__ wg_b,
                           float* __restrict__ qn, float* __restrict__ need,
                           float* __restrict__ sal, float* __restrict__ gate) {
    int l = blockIdx.x, t = threadIdx.x;
    __shared__ float r0[256], r1[256], r2[256], r3[256];
    float v = x[l * DM + t];
    r0[t] = v * v;
    r1[t] = v * unc_w[t];
    r2[t] = v * sal_w[t];
    r3[t] = v * wg_w[t];
    __syncthreads();
    for (int s = 128; s > 0; s >>= 1) {
        if (t < s) { r0[t] += r0[t + s]; r1[t] += r1[t + s]; r2[t] += r2[t + s]; r3[t] += r3[t + s]; }
        __syncthreads();
    }
    float norm = sqrtf(r0[0]);
    qn[l * DM + t] = v / fmaxf(norm, 1e-12f);
    if (t == 0) {
        need[l] = 1.f / (1.f + expf(-(r1[0] + unc_b[0])));
        sal[l]  = 1.f / (1.f + expf(-(r2[0] + sal_b[0])));
        gate[l] = 1.f / (1.f + expf(-(r3[0] + wg_b[0])));
    }
}

// ---------------- normalize memory keys ----------------
__global__ void k_knorm(const float* __restrict__ mk, float* __restrict__ kn) {
    int m = blockIdx.x, t = threadIdx.x;
    __shared__ float red[256];
    float v = mk[(size_t)m * DM + t];
    red[t] = v * v;
    __syncthreads();
    for (int s = 128; s > 0; s >>= 1) { if (t < s) red[t] += red[t + s]; __syncthreads(); }
    kn[(size_t)m * DM + t] = v / fmaxf(sqrtf(red[0]), 1e-12f);
}

// ---------------- row softmax over memory slots ----------------
__global__ void k_softmax_mem(float* __restrict__ res) {
    int l = blockIdx.x, t = threadIdx.x;
    __shared__ float red[256];
    float* row = res + (size_t)l * MMEM;
    float lm = -INFINITY;
    for (int m = t; m < MMEM; m += 256) lm = fmaxf(lm, row[m] * 5.0f);
    red[t] = lm; __syncthreads();
    for (int s = 128; s > 0; s >>= 1) { if (t < s) red[t] = fmaxf(red[t], red[t + s]); __syncthreads(); }
    float mx = red[0]; __syncthreads();
    float ls = 0.f;
    for (int m = t; m < MMEM; m += 256) { float p = expf(row[m] * 5.0f - mx); row[m] = p; ls += p; }
    red[t] = ls; __syncthreads();
    for (int s = 128; s > 0; s >>= 1) { if (t < s) red[t] += red[t + s]; __syncthreads(); }
    float inv = 1.f / red[0];
    __syncthreads();
    for (int m = t; m < MMEM; m += 256) row[m] *= inv;
}

// ---------------- retrieved *= need[l] ----------------
__global__ void k_need(float* __restrict__ ret, const float* __restrict__ need) {
    int idx = blockIdx.x * 256 + threadIdx.x;
    ret[idx] *= need[idx >> 8];
}

// ---------------- gate penalty ----------------
__global__ void k_penalty(const float* __restrict__ sal, const float* __restrict__ gate,
                          float* __restrict__ out) {
    __shared__ float s[LQ];
    __shared__ float rn[256], rc[256];
    int t = threadIdx.x;
    for (int l = t; l < LQ; l += 256) s[l] = sal[l];
    __syncthreads();
    float num = 0.f, cnt = 0.f;
    for (int l = t; l < LQ; l += 256) {
        float v = s[l];
        int j0 = l - 15 < 0 ? 0 : l - 15;
        int j1 = l + 15 > LQ - 1 ? LQ - 1 : l + 15;
        float mx = -INFINITY;
        for (int j = j0; j <= j1; j++) mx = fmaxf(mx, s[j]);
        if (v == mx && v > 0.15f) {
            float g = gate[l];
            num += (1.f - g) * (1.f - g);
            cnt += 1.f;
        }
    }
    rn[t] = num; rc[t] = cnt;
    __syncthreads();
    for (int st = 128; st > 0; st >>= 1) {
        if (t < st) { rn[t] += rn[t + st]; rc[t] += rc[t + st]; }
        __syncthreads();
    }
    if (t == 0) out[0] = rc[0] > 0.f ? rn[0] / fmaxf(rc[0], 1.f) : 0.f;
}

// ---------------- host side ----------------
static void gemm(const float* A, const float* B, const float* bias, const float* resid,
                 float* C, int Mm, int Nn, int Kk, int b_nt, int act, int fast) {
    dim3 grid((Nn + 127) / 128, Mm / 128, 1);
    k_gemm<<<grid, 256, GEMM_SMEM>>>(A, B, bias, resid, C, Mm, Nn, Kk, b_nt, act, Kk, fast);
}
static void gemm_splitk(const float* A, const float* B, const float* bias,
                        const float* resid, float* P, float* C,
                        int Mm, int Nn, int Kk, int b_nt, int nseg, int act, int fast) {
    dim3 grid((Nn + 127) / 128, Mm / 128, nseg);
    k_gemm<<<grid, 256, GEMM_SMEM>>>(A, B, nullptr, nullptr, P, Mm, Nn, Kk, b_nt, 0, Kk / nseg, fast);
    int total = Mm * Nn;
    k_sreduce<<<(total + 255) / 256, 256>>>(P, bias, resid, C, Nn, total, nseg, act);
}

extern "C" void kernel_launch(void* const* d_in, const int* in_sizes, int n_in,
                              void* d_out, int out_size) {
    const int*   tokens    = (const int*)d_in[0];
    const float* embed     = (const float*)d_in[1];
    const float* qkv_w     = (const float*)d_in[2];
    const float* qkv_b     = (const float*)d_in[3];
    const float* proj_w    = (const float*)d_in[4];
    const float* proj_b    = (const float*)d_in[5];
    const float* ln1_w     = (const float*)d_in[6];
    const float* mlp_w1    = (const float*)d_in[7];
    const float* mlp_b1    = (const float*)d_in[8];
    const float* mlp_w2    = (const float*)d_in[9];
    const float* mlp_b2    = (const float*)d_in[10];
    const float* ln2_w     = (const float*)d_in[11];
    const float* sal_w     = (const float*)d_in[12];
    const float* sal_b     = (const float*)d_in[13];
    const float* unc_w     = (const float*)d_in[14];
    const float* unc_b     = (const float*)d_in[15];
    const float* wg_w      = (const float*)d_in[16];
    const float* wg_b      = (const float*)d_in[17];
    const float* memproj_w = (const float*)d_in[18];
    const float* memproj_b = (const float*)d_in[19];
    const float* mem_k     = (const float*)d_in[20];
    const float* mem_v     = (const float*)d_in[21];
    float* out = (float*)d_out;

    cudaFuncSetAttribute(k_gemm, cudaFuncAttributeMaxDynamicSharedMemorySize, GEMM_SMEM);
    cudaFuncSetAttribute(k_attn2, cudaFuncAttributeMaxDynamicSharedMemorySize, ATTN_SMEM);

    float *x, *xn, *qkv, *o, *h1, *kn, *res, *ret, *xout, *split, *need, *sal, *gate;
    float *pacc, *pm, *pl;
    cudaGetSymbolAddress((void**)&x, g_x);
    cudaGetSymbolAddress((void**)&xn, g_xn);
    cudaGetSymbolAddress((void**)&qkv, g_qkv);
    cudaGetSymbolAddress((void**)&o, g_o);
    cudaGetSymbolAddress((void**)&h1, g_h1);
    cudaGetSymbolAddress((void**)&kn, g_kn);
    cudaGetSymbolAddress((void**)&res, g_res);
    cudaGetSymbolAddress((void**)&ret, g_ret);
    cudaGetSymbolAddress((void**)&xout, g_xout);
    cudaGetSymbolAddress((void**)&split, g_split);
    cudaGetSymbolAddress((void**)&need, g_need);
    cudaGetSymbolAddress((void**)&sal, g_sal);
    cudaGetSymbolAddress((void**)&gate, g_gate);
    cudaGetSymbolAddress((void**)&pacc, g_pacc);
    cudaGetSymbolAddress((void**)&pm, g_pm);
    cudaGetSymbolAddress((void**)&pl, g_pl);

    k_embed<<<(LQ * DM) / 256, 256>>>(tokens, embed, x);
    k_knorm<<<MMEM, 256>>>(mem_k, kn);

    for (int li = 0; li < NLAYER; li++) {
        k_rmsnorm<<<LQ, 256>>>(x, ln1_w + li * DM, xn);
        // qkv: split-K 4 -> 384 CTAs
        gemm_splitk(xn, qkv_w + (size_t)li * 3 * DM * DM, qkv_b + li * 3 * DM, nullptr,
                    split, qkv, LQ, 3 * DM, DM, 1, 4, 0, 0);
        k_rope<<<LQ, 128>>>(qkv);
        {
            dim3 g(80, NH);
            k_attn2<<<g, 256, ATTN_SMEM>>>(qkv, pacc, pm, pl);
            dim3 gc(LQ, NH);
            k_attn_comb<<<gc, 64>>>(pacc, pm, pl, o);
        }
        // proj: split-K 8 -> 256 CTAs
        gemm_splitk(o, proj_w + (size_t)li * DM * DM, proj_b + li * DM, x,
                    split, x, LQ, DM, DM, 1, 8, 0, 0);
        k_rmsnorm<<<LQ, 256>>>(x, ln2_w + li * DM, xn);
        // mlp1: split-K 2 -> 256 CTAs (gelu in reduce)
        gemm_splitk(xn, mlp_w1 + (size_t)li * DFF * DM, mlp_b1 + li * DFF, nullptr,
                    split, h1, LQ, DFF, DM, 1, 2, 1, 0);
        // mlp2: split-K 8 -> 256 CTAs
        gemm_splitk(h1, mlp_w2 + (size_t)li * DM * DFF, mlp_b2 + li * DM, x,
                    split, x, LQ, DM, DFF, 1, 8, 0, 0);
    }

    // landmark memory read
    k_rowstats<<<LQ, 256>>>(x, unc_w, unc_b, sal_w, sal_b, wg_w, wg_b,
                            xn, need, sal, gate);
    gemm(xn, kn, nullptr, nullptr, res, LQ, MMEM, DM, 1, 0, 0);
    k_softmax_mem<<<LQ, 256>>>(res);
    // ret feeds only output0 -> fast tf32
    gemm_splitk(res, mem_v, nullptr, nullptr, split, ret, LQ, DM, MMEM, 0, 8, 0, 1);
    k_need<<<(LQ * DM) / 256, 256>>>(ret, need);
    // memproj: split-K 8
    gemm_splitk(ret, memproj_w, memproj_b, x, split, xout, LQ, DM, DM, 1, 8, 0, 0);

    // tied-head logits: fast tf32 (xout is fp32-accurate; tolerance 1e-3)
    gemm(xout, embed, nullptr, nullptr, out, LQ, VOCAB, DM, 1, 0, 1);

    if (out_size > LQ * VOCAB)
        k_penalty<<<1, 256>>>(sal, gate, out + (size_t)LQ * VOCAB);
}

// round 10
// speedup vs baseline: 2.7877x; 1.0598x over previous
#include <cuda_runtime.h>
#include <math.h>
#include <stdint.h>

#define LQ 2048
#define DM 256
#define NH 4
#define HDIM 64
#define NLAYER 6
#define MMEM 8192
#define VOCAB 50257
#define DFF 1024

// ---------------- scratch (device globals: allocation-free) ----------------
__device__ float g_x[LQ * DM];
__device__ float g_xn[LQ * DM];
__device__ float g_qkv[LQ * 3 * DM];
__device__ float g_o[LQ * DM];
__device__ float g_h1[LQ * DFF];
__device__ float g_res[(size_t)LQ * MMEM];   // scores; softmax converts in-place to tf32 u32
__device__ float g_ret[LQ * DM];
__device__ float g_xout[LQ * DM];
__device__ float g_split[4 * LQ * 768];      // split-K partials (24 MB)
__device__ float g_need[LQ];
__device__ float g_sal[LQ];
__device__ float g_gate[LQ];
// pre-converted tf32 operands (u32)
__device__ uint32_t g_embu[VOCAB * DM];      // 51 MB
__device__ uint32_t g_qnu[LQ * DM];
__device__ uint32_t g_knu[MMEM * DM];        // 8 MB
__device__ uint32_t g_mvu[MMEM * DM];        // 8 MB
__device__ uint32_t g_xoutu[LQ * DM];
// flash-attention partials
__device__ float g_pacc[NH * 4 * LQ * HDIM];
__device__ float g_pm[NH * 4 * LQ];
__device__ float g_pl[NH * 4 * LQ];

__device__ __forceinline__ uint32_t f2tf32(float f) {
    uint32_t u;
    asm("cvt.rna.tf32.f32 %0, %1;" : "=r"(u) : "f"(f));
    return u;
}
__device__ __forceinline__ void tf32_split(float f, uint32_t& b, uint32_t& s) {
    b = f2tf32(f);
    s = f2tf32(f - __uint_as_float(b));
}
__device__ __forceinline__ void cp16(void* dst, const void* src, bool ok) {
    uint32_t sa = (uint32_t)__cvta_generic_to_shared(dst);
    int sz = ok ? 16 : 0;
    asm volatile("cp.async.ca.shared.global [%0], [%1], 16, %2;\n"
                 :: "r"(sa), "l"(src), "r"(sz));
}

#define MMA(c, A0, A1, A2, A3, B0, B1)                                        \
    asm volatile("mma.sync.aligned.m16n8k8.row.col.f32.tf32.tf32.f32 "        \
                 "{%0,%1,%2,%3}, {%4,%5,%6,%7}, {%8,%9}, {%0,%1,%2,%3};\n"    \
                 : "+f"(c[0]), "+f"(c[1]), "+f"(c[2]), "+f"(c[3])             \
                 : "r"(A0), "r"(A1), "r"(A2), "r"(A3), "r"(B0), "r"(B1))

// ---------------- elementwise float -> tf32 u32 ----------------
__global__ void k_fcvt(const float* __restrict__ in, uint32_t* __restrict__ ou, int n) {
    int i = blockIdx.x * 256 + threadIdx.x;
    if (i < n) ou[i] = f2tf32(in[i]);
}

// ---------------- embedding lookup ----------------
__global__ void k_embed(const int* __restrict__ tokens, const float* __restrict__ embed,
                        float* __restrict__ x) {
    int idx = blockIdx.x * 256 + threadIdx.x;
    int l = idx >> 8, d = idx & 255;
    x[idx] = embed[(size_t)tokens[l] * DM + d];
}

// ---------------- rmsnorm ----------------
__global__ void k_rmsnorm(const float* __restrict__ x, const float* __restrict__ w,
                          float* __restrict__ xn) {
    int l = blockIdx.x, t = threadIdx.x;
    __shared__ float red[256];
    float v = x[l * DM + t];
    red[t] = v * v;
    __syncthreads();
    for (int s = 128; s > 0; s >>= 1) {
        if (t < s) red[t] += red[t + s];
        __syncthreads();
    }
    float r = rsqrtf(red[0] / (float)DM + 1e-6f);
    xn[l * DM + t] = v * r * w[t];
}

// ---------------- accurate tf32x3 pipelined GEMM (float operands) ----------------
#define ASTRIDE 20
#define BSTRIDE 132
#define STG 2560
#define GEMM_SMEM (4 * STG * 4)
__global__ void __launch_bounds__(256, 2)
k_gemm(const float* __restrict__ A, const float* __restrict__ B,
       const float* __restrict__ bias, const float* __restrict__ resid,
       float* __restrict__ C, int Mm, int Nn, int Kk,
       int b_nt, int act, int kseg) {
    extern __shared__ float smem[];
    float* As = smem;
    float* Bs = smem + 2 * STG;

    const int n0 = blockIdx.x * 128, m0 = blockIdx.y * 128;
    const int tid = threadIdx.x;
    const int w = tid >> 5, lane = tid & 31;
    const int g = lane >> 2, l4 = lane & 3;
    const int warp_m = (w >> 2) * 64;
    const int warp_n = (w & 3) * 32;
    const int kbeg = blockIdx.z * kseg;
    const int kend = kbeg + kseg;

    float acc[4][4][4];
#pragma unroll
    for (int i = 0; i < 4; i++)
#pragma unroll
        for (int j = 0; j < 4; j++)
#pragma unroll
            for (int r = 0; r < 4; r++) acc[i][j][r] = 0.f;

    auto load_tiles = [&](int k0, int st) {
        {
            int row = tid >> 1, colb = (tid & 1) * 8;
            const float* src = A + (size_t)(m0 + row) * Kk + k0 + colb;
            float* dst = As + st * STG + row * ASTRIDE + colb;
            cp16(dst, src, true);
            cp16(dst + 4, src + 4, true);
        }
        if (b_nt) {
            int row = tid >> 1, colb = (tid & 1) * 8;
            int gn = n0 + row;
            bool ok = gn < Nn;
            const float* src = B + (size_t)(ok ? gn : 0) * Kk + k0 + colb;
            float* dst = Bs + st * STG + row * ASTRIDE + colb;
            cp16(dst, src, ok);
            cp16(dst + 4, src + 4, ok);
        } else {
            int k = tid >> 4, colb = (tid & 15) * 8;
            const float* src = B + (size_t)(k0 + k) * Nn + n0 + colb;
            float* dst = Bs + st * STG + k * BSTRIDE + colb;
            cp16(dst, src, true);
            cp16(dst + 4, src + 4, true);
        }
        asm volatile("cp.async.commit_group;\n");
    };

    load_tiles(kbeg, 0);
    int stage = 0;
    for (int k0 = kbeg; k0 < kend; k0 += 16) {
        bool more = (k0 + 16) < kend;
        if (more) {
            load_tiles(k0 + 16, stage ^ 1);
            asm volatile("cp.async.wait_group 1;\n");
        } else {
            asm volatile("cp.async.wait_group 0;\n");
        }
        __syncthreads();

        const float* Af = As + stage * STG;
        const float* Bf = Bs + stage * STG;
#pragma unroll
        for (int ks = 0; ks < 2; ks++) {
            const int kc = ks * 8;
            uint32_t ab[4][4], ax[4][4], bb[4][2], bx[4][2];
#pragma unroll
            for (int mt = 0; mt < 4; mt++) {
                int r = (warp_m + mt * 16 + g) * ASTRIDE + kc + l4;
                tf32_split(Af[r],                   ab[mt][0], ax[mt][0]);
                tf32_split(Af[r + 8 * ASTRIDE],     ab[mt][1], ax[mt][1]);
                tf32_split(Af[r + 4],               ab[mt][2], ax[mt][2]);
                tf32_split(Af[r + 8 * ASTRIDE + 4], ab[mt][3], ax[mt][3]);
            }
            if (b_nt) {
#pragma unroll
                for (int nt = 0; nt < 4; nt++) {
                    int r = (warp_n + nt * 8 + g) * ASTRIDE + kc + l4;
                    tf32_split(Bf[r],     bb[nt][0], bx[nt][0]);
                    tf32_split(Bf[r + 4], bb[nt][1], bx[nt][1]);
                }
            } else {
#pragma unroll
                for (int nt = 0; nt < 4; nt++) {
                    int cn = warp_n + nt * 8 + g;
                    tf32_split(Bf[(kc + l4) * BSTRIDE + cn],     bb[nt][0], bx[nt][0]);
                    tf32_split(Bf[(kc + l4 + 4) * BSTRIDE + cn], bb[nt][1], bx[nt][1]);
                }
            }
#pragma unroll
            for (int mt = 0; mt < 4; mt++)
#pragma unroll
                for (int nt = 0; nt < 4; nt++)
                    MMA(acc[mt][nt], ab[mt][0], ab[mt][1], ab[mt][2], ab[mt][3],
                        bb[nt][0], bb[nt][1]);
#pragma unroll
            for (int mt = 0; mt < 4; mt++)
#pragma unroll
                for (int nt = 0; nt < 4; nt++)
                    MMA(acc[mt][nt], ab[mt][0], ab[mt][1], ab[mt][2], ab[mt][3],
                        bx[nt][0], bx[nt][1]);
#pragma unroll
            for (int mt = 0; mt < 4; mt++)
#pragma unroll
                for (int nt = 0; nt < 4; nt++)
                    MMA(acc[mt][nt], ax[mt][0], ax[mt][1], ax[mt][2], ax[mt][3],
                        bb[nt][0], bb[nt][1]);
        }
        __syncthreads();
        stage ^= 1;
    }

    bool partial = (gridDim.z > 1);
    float* Cw = partial ? C + (size_t)blockIdx.z * Mm * Nn : C;
#pragma unroll
    for (int mt = 0; mt < 4; mt++) {
#pragma unroll
        for (int nt = 0; nt < 4; nt++) {
#pragma unroll
            for (int half = 0; half < 2; half++) {
                int m = m0 + warp_m + mt * 16 + g + half * 8;
#pragma unroll
                for (int cc = 0; cc < 2; cc++) {
                    int n = n0 + warp_n + nt * 8 + l4 * 2 + cc;
                    if (n < Nn) {
                        float c = acc[mt][nt][half * 2 + cc];
                        if (!partial) {
                            if (bias) c += bias[n];
                            if (resid) c += resid[(size_t)m * Nn + n];
                            if (act == 1) c = 0.5f * c * (1.0f + erff(c * 0.70710678118654752f));
                        }
                        Cw[(size_t)m * Nn + n] = c;
                    }
                }
            }
        }
    }
}

// ---------------- pre-converted tf32 GEMM (u32 operands, 1x MMA) ----------------
__global__ void __launch_bounds__(256, 2)
k_gemmp(const uint32_t* __restrict__ A, const uint32_t* __restrict__ B,
        float* __restrict__ C, int Mm, int Nn, int Kk, int b_nt, int kseg) {
    extern __shared__ uint32_t smu[];
    uint32_t* As = smu;
    uint32_t* Bs = smu + 2 * STG;

    const int n0 = blockIdx.x * 128, m0 = blockIdx.y * 128;
    const int tid = threadIdx.x;
    const int w = tid >> 5, lane = tid & 31;
    const int g = lane >> 2, l4 = lane & 3;
    const int warp_m = (w >> 2) * 64;
    const int warp_n = (w & 3) * 32;
    const int kbeg = blockIdx.z * kseg;
    const int kend = kbeg + kseg;

    float acc[4][4][4];
#pragma unroll
    for (int i = 0; i < 4; i++)
#pragma unroll
        for (int j = 0; j < 4; j++)
#pragma unroll
            for (int r = 0; r < 4; r++) acc[i][j][r] = 0.f;

    auto load_tiles = [&](int k0, int st) {
        {
            int row = tid >> 1, colb = (tid & 1) * 8;
            const uint32_t* src = A + (size_t)(m0 + row) * Kk + k0 + colb;
            uint32_t* dst = As + st * STG + row * ASTRIDE + colb;
            cp16(dst, src, true);
            cp16(dst + 4, src + 4, true);
        }
        if (b_nt) {
            int row = tid >> 1, colb = (tid & 1) * 8;
            int gn = n0 + row;
            bool ok = gn < Nn;
            const uint32_t* src = B + (size_t)(ok ? gn : 0) * Kk + k0 + colb;
            uint32_t* dst = Bs + st * STG + row * ASTRIDE + colb;
            cp16(dst, src, ok);
            cp16(dst + 4, src + 4, ok);
        } else {
            int k = tid >> 4, colb = (tid & 15) * 8;
            const uint32_t* src = B + (size_t)(k0 + k) * Nn + n0 + colb;
            uint32_t* dst = Bs + st * STG + k * BSTRIDE + colb;
            cp16(dst, src, true);
            cp16(dst + 4, src + 4, true);
        }
        asm volatile("cp.async.commit_group;\n");
    };

    load_tiles(kbeg, 0);
    int stage = 0;
    for (int k0 = kbeg; k0 < kend; k0 += 16) {
        bool more = (k0 + 16) < kend;
        if (more) {
            load_tiles(k0 + 16, stage ^ 1);
            asm volatile("cp.async.wait_group 1;\n");
        } else {
            asm volatile("cp.async.wait_group 0;\n");
        }
        __syncthreads();

        const uint32_t* Af = As + stage * STG;
        const uint32_t* Bf = Bs + stage * STG;
#pragma unroll
        for (int ks = 0; ks < 2; ks++) {
            const int kc = ks * 8;
            uint32_t ab[4][4], bb[4][2];
#pragma unroll
            for (int mt = 0; mt < 4; mt++) {
                int r = (warp_m + mt * 16 + g) * ASTRIDE + kc + l4;
                ab[mt][0] = Af[r];
                ab[mt][1] = Af[r + 8 * ASTRIDE];
                ab[mt][2] = Af[r + 4];
                ab[mt][3] = Af[r + 8 * ASTRIDE + 4];
            }
            if (b_nt) {
#pragma unroll
                for (int nt = 0; nt < 4; nt++) {
                    int r = (warp_n + nt * 8 + g) * ASTRIDE + kc + l4;
                    bb[nt][0] = Bf[r];
                    bb[nt][1] = Bf[r + 4];
                }
            } else {
#pragma unroll
                for (int nt = 0; nt < 4; nt++) {
                    int cn = warp_n + nt * 8 + g;
                    bb[nt][0] = Bf[(kc + l4) * BSTRIDE + cn];
                    bb[nt][1] = Bf[(kc + l4 + 4) * BSTRIDE + cn];
                }
            }
#pragma unroll
            for (int mt = 0; mt < 4; mt++)
#pragma unroll
                for (int nt = 0; nt < 4; nt++)
                    MMA(acc[mt][nt], ab[mt][0], ab[mt][1], ab[mt][2], ab[mt][3],
                        bb[nt][0], bb[nt][1]);
        }
        __syncthreads();
        stage ^= 1;
    }

    bool partial = (gridDim.z > 1);
    float* Cw = partial ? C + (size_t)blockIdx.z * Mm * Nn : C;
#pragma unroll
    for (int mt = 0; mt < 4; mt++) {
#pragma unroll
        for (int nt = 0; nt < 4; nt++) {
#pragma unroll
            for (int half = 0; half < 2; half++) {
                int m = m0 + warp_m + mt * 16 + g + half * 8;
#pragma unroll
                for (int cc = 0; cc < 2; cc++) {
                    int n = n0 + warp_n + nt * 8 + l4 * 2 + cc;
                    if (n < Nn)
                        Cw[(size_t)m * Nn + n] = acc[mt][nt][half * 2 + cc];
                }
            }
        }
    }
}

// ---------------- split-K reduction ----------------
__global__ void k_sreduce(const float* __restrict__ P, const float* __restrict__ bias,
                          const float* __restrict__ resid, float* __restrict__ C,
                          int Nn, int total, int nseg, int act) {
    int idx = blockIdx.x * 256 + threadIdx.x;
    if (idx >= total) return;
    float s = 0.f;
    for (int z = 0; z < nseg; z++) s += P[(size_t)z * total + idx];
    int n = idx % Nn;
    if (bias) s += bias[n];
    if (resid) s += resid[idx];
    if (act == 1) s = 0.5f * s * (1.0f + erff(s * 0.70710678118654752f));
    C[idx] = s;
}

// ---------------- RoPE ----------------
__global__ void k_rope(float* __restrict__ qkv) {
    int l = blockIdx.x, t = threadIdx.x;
    int h = t >> 5, i = t & 31;
    float inv = (float)pow(10000.0, -(double)(2 * i) / (double)HDIM);
    float ang = (float)l * inv;
    float s, c;
    sincosf(ang, &s, &c);
    float* qp = qkv + (size_t)l * 768 + h * HDIM + 2 * i;
    float q0 = qp[0], q1 = qp[1];
    qp[0] = q0 * c - q1 * s;
    qp[1] = q0 * s + q1 * c;
    float* kp = qp + DM;
    float k0 = kp[0], k1 = kp[1];
    kp[0] = k0 * c - k1 * s;
    kp[1] = k0 * s + k1 * c;
}

// ---------------- flash attention partials ----------------
#define ASTR 72
#define ATTN_SMEM (4 * 64 * ASTR * 4)
__global__ void __launch_bounds__(256)
k_attn2(const float* __restrict__ qkv, float* __restrict__ pacc,
        float* __restrict__ pm, float* __restrict__ pl) {
    extern __shared__ float sf[];
    float* Qs = sf;
    float* Ks = sf + 64 * ASTR;
    float* Vs = sf + 2 * 64 * ASTR;
    float* Ps = sf + 3 * 64 * ASTR;

    int bx = blockIdx.x, h = blockIdx.y;
    int qb = 0, c = 0;
    {
        int accum = 0;
        for (int i = 0; i < 32; i++) {
            int nch = (i >> 3) + 1;
            if (bx < accum + nch) { qb = i; c = bx - accum; break; }
            accum += nch;
        }
    }
    const int q0 = qb * 64;
    const int tid = threadIdx.x;
    const int ty = tid >> 4, tx = tid & 15;
    const int lr = tid >> 2, lseg = (tid & 3) * 16;

    {
        const float4* src = (const float4*)(qkv + (size_t)(q0 + lr) * 768 + h * HDIM + lseg);
        float4* dst = (float4*)(Qs + lr * ASTR + lseg);
#pragma unroll
        for (int i = 0; i < 4; i++) dst[i] = src[i];
    }

    float m_[4], l_[4], acc[4][4];
#pragma unroll
    for (int i = 0; i < 4; i++) {
        m_[i] = -INFINITY; l_[i] = 0.f;
#pragma unroll
        for (int j = 0; j < 4; j++) acc[i][j] = 0.f;
    }

    int t0 = c * 8, t1 = min(c * 8 + 8, qb + 1);
    for (int t = t0; t < t1; t++) {
        int k0 = t * 64;
        {
            const float4* sk = (const float4*)(qkv + (size_t)(k0 + lr) * 768 + DM + h * HDIM + lseg);
            const float4* sv = (const float4*)(qkv + (size_t)(k0 + lr) * 768 + 2 * DM + h * HDIM + lseg);
            float4* dk = (float4*)(Ks + lr * ASTR + lseg);
            float4* dv = (float4*)(Vs + lr * ASTR + lseg);
#pragma unroll
            for (int i = 0; i < 4; i++) { dk[i] = sk[i]; dv[i] = sv[i]; }
        }
        __syncthreads();

        float s[4][4] = {};
#pragma unroll
        for (int d4 = 0; d4 < HDIM; d4 += 4) {
            float4 q4[4], k4[4];
#pragma unroll
            for (int i = 0; i < 4; i++) q4[i] = *(const float4*)(Qs + (ty * 4 + i) * ASTR + d4);
#pragma unroll
            for (int j = 0; j < 4; j++) k4[j] = *(const float4*)(Ks + (tx * 4 + j) * ASTR + d4);
#pragma unroll
            for (int i = 0; i < 4; i++)
#pragma unroll
                for (int j = 0; j < 4; j++)
                    s[i][j] += q4[i].x * k4[j].x + q4[i].y * k4[j].y +
                               q4[i].z * k4[j].z + q4[i].w * k4[j].w;
        }
#pragma unroll
        for (int i = 0; i < 4; i++)
#pragma unroll
            for (int j = 0; j < 4; j++) {
                s[i][j] *= 0.125f;
                if (k0 + tx * 4 + j > q0 + ty * 4 + i) s[i][j] = -INFINITY;
            }
#pragma unroll
        for (int i = 0; i < 4; i++) {
            float mt = fmaxf(fmaxf(s[i][0], s[i][1]), fmaxf(s[i][2], s[i][3]));
#pragma unroll
            for (int sh = 8; sh > 0; sh >>= 1) mt = fmaxf(mt, __shfl_xor_sync(0xffffffffu, mt, sh));
            float mn = fmaxf(m_[i], mt);
            float alpha = expf(m_[i] - mn);
            float p0 = expf(s[i][0] - mn), p1 = expf(s[i][1] - mn);
            float p2 = expf(s[i][2] - mn), p3 = expf(s[i][3] - mn);
            float rs = p0 + p1 + p2 + p3;
#pragma unroll
            for (int sh = 8; sh > 0; sh >>= 1) rs += __shfl_xor_sync(0xffffffffu, rs, sh);
            l_[i] = l_[i] * alpha + rs;
            m_[i] = mn;
#pragma unroll
            for (int j = 0; j < 4; j++) acc[i][j] *= alpha;
            *(float4*)(Ps + (ty * 4 + i) * ASTR + tx * 4) = make_float4(p0, p1, p2, p3);
        }
        __syncthreads();
#pragma unroll
        for (int k4i = 0; k4i < 64; k4i += 4) {
            float4 pv[4], v4[4];
#pragma unroll
            for (int i = 0; i < 4; i++) pv[i] = *(const float4*)(Ps + (ty * 4 + i) * ASTR + k4i);
#pragma unroll
            for (int kk = 0; kk < 4; kk++) v4[kk] = *(const float4*)(Vs + (k4i + kk) * ASTR + tx * 4);
#pragma unroll
            for (int i = 0; i < 4; i++) {
                acc[i][0] += pv[i].x * v4[0].x + pv[i].y * v4[1].x + pv[i].z * v4[2].x + pv[i].w * v4[3].x;
                acc[i][1] += pv[i].x * v4[0].y + pv[i].y * v4[1].y + pv[i].z * v4[2].y + pv[i].w * v4[3].y;
                acc[i][2] += pv[i].x * v4[0].z + pv[i].y * v4[1].z + pv[i].z * v4[2].z + pv[i].w * v4[3].z;
                acc[i][3] += pv[i].x * v4[0].w + pv[i].y * v4[1].w + pv[i].z * v4[2].w + pv[i].w * v4[3].w;
            }
        }
        __syncthreads();
    }

    int base = (h * 4 + c) * LQ;
#pragma unroll
    for (int i = 0; i < 4; i++) {
        int q = q0 + ty * 4 + i;
        if (tx == 0) { pm[base + q] = m_[i]; pl[base + q] = l_[i]; }
        *(float4*)(pacc + ((size_t)(base + q)) * HDIM + tx * 4) =
            make_float4(acc[i][0], acc[i][1], acc[i][2], acc[i][3]);
    }
}

// ---------------- combine attention partials -> o ----------------
__global__ void k_attn_comb(const float* __restrict__ pacc, const float* __restrict__ pm,
                            const float* __restrict__ pl, float* __restrict__ o) {
    int q = blockIdx.x, h = blockIdx.y, d = threadIdx.x;
    int nch = ((q >> 6) >> 3) + 1;
    float M = -INFINITY;
    for (int c = 0; c < nch; c++) M = fmaxf(M, pm[(h * 4 + c) * LQ + q]);
    float L = 0.f, A = 0.f;
    for (int c = 0; c < nch; c++) {
        float wgt = expf(pm[(h * 4 + c) * LQ + q] - M);
        L += pl[(h * 4 + c) * LQ + q] * wgt;
        A += pacc[((size_t)((h * 4 + c) * LQ + q)) * HDIM + d] * wgt;
    }
    o[(size_t)q * DM + h * HDIM + d] = A / L;
}

// ---------------- row stats: qn as tf32 u32 + need/sal/gate ----------------
__global__ void k_rowstats(const float* __restrict__ x,
                           const float* __restrict__ unc_w, const float* __restrict__ unc_b,
                           const float* __restrict__ sal_w, const float* __restrict__ sal_b,
                           const float* __restrict__ wg_w, const float* __restrict__ wg_b,
                           uint32_t* __restrict__ qnu, float* __restrict__ need,
                           float* __restrict__ sal, float* __restrict__ gate) {
    int l = blockIdx.x, t = threadIdx.x;
    __shared__ float r0[256], r1[256], r2[256], r3[256];
    float v = x[l * DM + t];
    r0[t] = v * v;
    r1[t] = v * unc_w[t];
    r2[t] = v * sal_w[t];
    r3[t] = v * wg_w[t];
    __syncthreads();
    for (int s = 128; s > 0; s >>= 1) {
        if (t < s) { r0[t] += r0[t + s]; r1[t] += r1[t + s]; r2[t] += r2[t + s]; r3[t] += r3[t + s]; }
        __syncthreads();
    }
    float norm = sqrtf(r0[0]);
    qnu[l * DM + t] = f2tf32(v / fmaxf(norm, 1e-12f));
    if (t == 0) {
        need[l] = 1.f / (1.f + expf(-(r1[0] + unc_b[0])));
        sal[l]  = 1.f / (1.f + expf(-(r2[0] + sal_b[0])));
        gate[l] = 1.f / (1.f + expf(-(r3[0] + wg_b[0])));
    }
}

// ---------------- normalize memory keys -> tf32 u32 ----------------
__global__ void k_knorm(const float* __restrict__ mk, uint32_t* __restrict__ knu) {
    int m = blockIdx.x, t = threadIdx.x;
    __shared__ float red[256];
    float v = mk[(size_t)m * DM + t];
    red[t] = v * v;
    __syncthreads();
    for (int s = 128; s > 0; s >>= 1) { if (t < s) red[t] += red[t + s]; __syncthreads(); }
    knu[(size_t)m * DM + t] = f2tf32(v / fmaxf(sqrtf(red[0]), 1e-12f));
}

// ---------------- memory softmax: normalize + in-place convert to tf32 u32 ----------------
__global__ void k_softmax_mem(float* __restrict__ res) {
    int l = blockIdx.x, t = threadIdx.x;
    __shared__ float red[256];
    float* row = res + (size_t)l * MMEM;
    uint32_t* rowu = (uint32_t*)row;
    float lm = -INFINITY;
    for (int m = t; m < MMEM; m += 256) lm = fmaxf(lm, row[m] * 5.0f);
    red[t] = lm; __syncthreads();
    for (int s = 128; s > 0; s >>= 1) { if (t < s) red[t] = fmaxf(red[t], red[t + s]); __syncthreads(); }
    float mx = red[0]; __syncthreads();
    float ls = 0.f;
    for (int m = t; m < MMEM; m += 256) { float p = expf(row[m] * 5.0f - mx); row[m] = p; ls += p; }
    red[t] = ls; __syncthreads();
    for (int s = 128; s > 0; s >>= 1) { if (t < s) red[t] += red[t + s]; __syncthreads(); }
    float inv = 1.f / red[0];
    __syncthreads();
    for (int m = t; m < MMEM; m += 256) rowu[m] = f2tf32(row[m] * inv);
}

// ---------------- retrieved *= need[l] ----------------
__global__ void k_need(float* __restrict__ ret, const float* __restrict__ need) {
    int idx = blockIdx.x * 256 + threadIdx.x;
    ret[idx] *= need[idx >> 8];
}

// ---------------- gate penalty ----------------
__global__ void k_penalty(const float* __restrict__ sal, const float* __restrict__ gate,
                          float* __restrict__ out) {
    __shared__ float s[LQ];
    __shared__ float rn[256], rc[256];
    int t = threadIdx.x;
    for (int l = t; l < LQ; l += 256) s[l] = sal[l];
    __syncthreads();
    float num = 0.f, cnt = 0.f;
    for (int l = t; l < LQ; l += 256) {
        float v = s[l];
        int j0 = l - 15 < 0 ? 0 : l - 15;
        int j1 = l + 15 > LQ - 1 ? LQ - 1 : l + 15;
        float mx = -INFINITY;
        for (int j = j0; j <= j1; j++) mx = fmaxf(mx, s[j]);
        if (v == mx && v > 0.15f) {
            float g = gate[l];
            num += (1.f - g) * (1.f - g);
            cnt += 1.f;
        }
    }
    rn[t] = num; rc[t] = cnt;
    __syncthreads();
    for (int st = 128; st > 0; st >>= 1) {
        if (t < st) { rn[t] += rn[t + st]; rc[t] += rc[t + st]; }
        __syncthreads();
    }
    if (t == 0) out[0] = rc[0] > 0.f ? rn[0] / fmaxf(rc[0], 1.f) : 0.f;
}

// ---------------- host side ----------------
static void gemm(const float* A, const float* B, const float* bias, const float* resid,
                 float* C, int Mm, int Nn, int Kk, int b_nt, int act) {
    dim3 grid((Nn + 127) / 128, Mm / 128, 1);
    k_gemm<<<grid, 256, GEMM_SMEM>>>(A, B, bias, resid, C, Mm, Nn, Kk, b_nt, act, Kk);
}
static void gemm_splitk(const float* A, const float* B, const float* bias,
                        const float* resid, float* P, float* C,
                        int Mm, int Nn, int Kk, int b_nt, int nseg, int act) {
    dim3 grid((Nn + 127) / 128, Mm / 128, nseg);
    k_gemm<<<grid, 256, GEMM_SMEM>>>(A, B, nullptr, nullptr, P, Mm, Nn, Kk, b_nt, 0, Kk / nseg);
    int total = Mm * Nn;
    k_sreduce<<<(total + 255) / 256, 256>>>(P, bias, resid, C, Nn, total, nseg, act);
}
static void gemmp(const uint32_t* A, const uint32_t* B, float* C,
                  int Mm, int Nn, int Kk, int b_nt) {
    dim3 grid((Nn + 127) / 128, Mm / 128, 1);
    k_gemmp<<<grid, 256, GEMM_SMEM>>>(A, B, C, Mm, Nn, Kk, b_nt, Kk);
}
static void gemmp_splitk(const uint32_t* A, const uint32_t* B, float* P, float* C,
                         int Mm, int Nn, int Kk, int b_nt, int nseg) {
    dim3 grid((Nn + 127) / 128, Mm / 128, nseg);
    k_gemmp<<<grid, 256, GEMM_SMEM>>>(A, B, P, Mm, Nn, Kk, b_nt, Kk / nseg);
    int total = Mm * Nn;
    k_sreduce<<<(total + 255) / 256, 256>>>(P, nullptr, nullptr, C, Nn, total, nseg, 0);
}

extern "C" void kernel_launch(void* const* d_in, const int* in_sizes, int n_in,
                              void* d_out, int out_size) {
    const int*   tokens    = (const int*)d_in[0];
    const float* embed     = (const float*)d_in[1];
    const float* qkv_w     = (const float*)d_in[2];
    const float* qkv_b     = (const float*)d_in[3];
    const float* proj_w    = (const float*)d_in[4];
    const float* proj_b    = (const float*)d_in[5];
    const float* ln1_w     = (const float*)d_in[6];
    const float* mlp_w1    = (const float*)d_in[7];
    const float* mlp_b1    = (const float*)d_in[8];
    const float* mlp_w2    = (const float*)d_in[9];
    const float* mlp_b2    = (const float*)d_in[10];
    const float* ln2_w     = (const float*)d_in[11];
    const float* sal_w     = (const float*)d_in[12];
    const float* sal_b     = (const float*)d_in[13];
    const float* unc_w     = (const float*)d_in[14];
    const float* unc_b     = (const float*)d_in[15];
    const float* wg_w      = (const float*)d_in[16];
    const float* wg_b      = (const float*)d_in[17];
    const float* memproj_w = (const float*)d_in[18];
    const float* memproj_b = (const float*)d_in[19];
    const float* mem_k     = (const float*)d_in[20];
    const float* mem_v     = (const float*)d_in[21];
    float* out = (float*)d_out;

    cudaFuncSetAttribute(k_gemm, cudaFuncAttributeMaxDynamicSharedMemorySize, GEMM_SMEM);
    cudaFuncSetAttribute(k_gemmp, cudaFuncAttributeMaxDynamicSharedMemorySize, GEMM_SMEM);
    cudaFuncSetAttribute(k_attn2, cudaFuncAttributeMaxDynamicSharedMemorySize, ATTN_SMEM);

    float *x, *xn, *qkv, *o, *h1, *res, *ret, *xout, *split, *need, *sal, *gate;
    float *pacc, *pm, *pl;
    uint32_t *embu, *qnu, *knu, *mvu, *xoutu;
    cudaGetSymbolAddress((void**)&x, g_x);
    cudaGetSymbolAddress((void**)&xn, g_xn);
    cudaGetSymbolAddress((void**)&qkv, g_qkv);
    cudaGetSymbolAddress((void**)&o, g_o);
    cudaGetSymbolAddress((void**)&h1, g_h1);
    cudaGetSymbolAddress((void**)&res, g_res);
    cudaGetSymbolAddress((void**)&ret, g_ret);
    cudaGetSymbolAddress((void**)&xout, g_xout);
    cudaGetSymbolAddress((void**)&split, g_split);
    cudaGetSymbolAddress((void**)&need, g_need);
    cudaGetSymbolAddress((void**)&sal, g_sal);
    cudaGetSymbolAddress((void**)&gate, g_gate);
    cudaGetSymbolAddress((void**)&pacc, g_pacc);
    cudaGetSymbolAddress((void**)&pm, g_pm);
    cudaGetSymbolAddress((void**)&pl, g_pl);
    cudaGetSymbolAddress((void**)&embu, g_embu);
    cudaGetSymbolAddress((void**)&qnu, g_qnu);
    cudaGetSymbolAddress((void**)&knu, g_knu);
    cudaGetSymbolAddress((void**)&mvu, g_mvu);
    cudaGetSymbolAddress((void**)&xoutu, g_xoutu);

    // one-time conversions (overlap with layer work via same stream ordering)
    k_embed<<<(LQ * DM) / 256, 256>>>(tokens, embed, x);
    k_fcvt<<<(VOCAB * DM + 255) / 256, 256>>>(embed, embu, VOCAB * DM);
    k_fcvt<<<(MMEM * DM + 255) / 256, 256>>>(mem_v, mvu, MMEM * DM);
    k_knorm<<<MMEM, 256>>>(mem_k, knu);

    for (int li = 0; li < NLAYER; li++) {
        k_rmsnorm<<<LQ, 256>>>(x, ln1_w + li * DM, xn);
        // qkv: split-K 2 (nseg=4 measured slower)
        gemm_splitk(xn, qkv_w + (size_t)li * 3 * DM * DM, qkv_b + li * 3 * DM, nullptr,
                    split, qkv, LQ, 3 * DM, DM, 1, 2, 0);
        k_rope<<<LQ, 128>>>(qkv);
        {
            dim3 g(80, NH);
            k_attn2<<<g, 256, ATTN_SMEM>>>(qkv, pacc, pm, pl);
            dim3 gc(LQ, NH);
            k_attn_comb<<<gc, 64>>>(pacc, pm, pl, o);
        }
        gemm_splitk(o, proj_w + (size_t)li * DM * DM, proj_b + li * DM, x,
                    split, x, LQ, DM, DM, 1, 8, 0);
        k_rmsnorm<<<LQ, 256>>>(x, ln2_w + li * DM, xn);
        gemm_splitk(xn, mlp_w1 + (size_t)li * DFF * DM, mlp_b1 + li * DFF, nullptr,
                    split, h1, LQ, DFF, DM, 1, 2, 1);
        gemm_splitk(h1, mlp_w2 + (size_t)li * DM * DFF, mlp_b2 + li * DM, x,
                    split, x, LQ, DM, DFF, 1, 8, 0);
    }

    // landmark memory read (fast tier: feeds only output0)
    k_rowstats<<<LQ, 256>>>(x, unc_w, unc_b, sal_w, sal_b, wg_w, wg_b,
                            qnu, need, sal, gate);
    gemmp(qnu, knu, res, LQ, MMEM, DM, 1);
    k_softmax_mem<<<LQ, 256>>>(res);   // normalizes + converts in-place to tf32 u32
    gemmp_splitk((const uint32_t*)res, mvu, split, ret, LQ, DM, MMEM, 0, 8);
    k_need<<<(LQ * DM) / 256, 256>>>(ret, need);
    // memproj stays accurate (xout adds to x; keep fp32 fidelity of the additive path)
    gemm_splitk(ret, memproj_w, memproj_b, x, split, xout, LQ, DM, DM, 1, 8, 0);
    k_fcvt<<<(LQ * DM + 255) / 256, 256>>>(xout, xoutu, LQ * DM);

    // tied-head logits (fast tier, pre-converted)
    gemmp(xoutu, embu, out, LQ, VOCAB, DM, 1);

    if (out_size > LQ * VOCAB)
        k_penalty<<<1, 256>>>(sal, gate, out + (size_t)LQ * VOCAB);
}